// round 1
// baseline (speedup 1.0000x reference)
#include <cuda_runtime.h>
#include <math.h>

// Problem constants
#define Bc 4
#define Sc 4096
#define Dc 1024
#define Hc 16
#define Rc 256
#define HDc 64
#define Mtot (Bc * Sc)          // 16384 rows for the big GEMMs

// ---------------------------------------------------------------------------
// Scratch (device globals -- no runtime allocation allowed)
// ---------------------------------------------------------------------------
__device__ float g_q[(size_t)Mtot * Dc];                 // 64 MB  [b,s,D]
__device__ float g_k[(size_t)Mtot * Dc];                 // 64 MB
__device__ float g_v[(size_t)Mtot * Dc];                 // 64 MB
__device__ float g_qp[(size_t)Bc * Hc * Sc * Rc];        // 64 MB  [bh,s,r]
__device__ float g_kp[(size_t)Bc * Hc * Sc * Rc];        // 64 MB
__device__ float g_kvagg[(size_t)Bc * Hc * Rc * HDc];    // 4 MB   [bh,r,d]
__device__ float g_ksum[(size_t)Bc * Hc * Rc];           // 64 KB  [bh,r]
__device__ float g_attn[(size_t)Mtot * Dc];              // 64 MB  [b,s,D]

// ---------------------------------------------------------------------------
// Kernel 1: C[m,n] = sum_k A[m,k] * B[n,k] + bias[n]      (NT GEMM, fp32)
// A:[M,K] row-major, B:[N,K] row-major. M%128==0, N%128==0, K%8==0 assumed.
// 128x128 block tile, 8x8 per thread, BK=8.
// ---------------------------------------------------------------------------
__global__ void __launch_bounds__(256)
sgemm_nt_bias(const float* __restrict__ A, const float* __restrict__ B,
              const float* __restrict__ bias, float* __restrict__ C,
              int M, int N, int K)
{
    __shared__ float As[8][128];
    __shared__ float Bs[8][128];

    const int tid = threadIdx.x;
    const int tx = tid & 15;          // column group (8 cols)
    const int ty = tid >> 4;          // row group (8 rows)
    const int m0 = blockIdx.y << 7;
    const int n0 = blockIdx.x << 7;

    const int lrow = tid >> 1;        // 0..127
    const int lk   = (tid & 1) << 2;  // 0 or 4
    const float* Ag = A + (size_t)(m0 + lrow) * K + lk;
    const float* Bg = B + (size_t)(n0 + lrow) * K + lk;

    float acc[8][8];
    #pragma unroll
    for (int i = 0; i < 8; i++)
        #pragma unroll
        for (int j = 0; j < 8; j++) acc[i][j] = 0.0f;

    for (int k0 = 0; k0 < K; k0 += 8) {
        float4 av = *(const float4*)(Ag + k0);
        float4 bv = *(const float4*)(Bg + k0);
        As[lk + 0][lrow] = av.x; As[lk + 1][lrow] = av.y;
        As[lk + 2][lrow] = av.z; As[lk + 3][lrow] = av.w;
        Bs[lk + 0][lrow] = bv.x; Bs[lk + 1][lrow] = bv.y;
        Bs[lk + 2][lrow] = bv.z; Bs[lk + 3][lrow] = bv.w;
        __syncthreads();
        #pragma unroll
        for (int kk = 0; kk < 8; kk++) {
            float a[8], b[8];
            *(float4*)(a)     = *(const float4*)(&As[kk][ty << 3]);
            *(float4*)(a + 4) = *(const float4*)(&As[kk][(ty << 3) + 4]);
            *(float4*)(b)     = *(const float4*)(&Bs[kk][tx << 3]);
            *(float4*)(b + 4) = *(const float4*)(&Bs[kk][(tx << 3) + 4]);
            #pragma unroll
            for (int i = 0; i < 8; i++)
                #pragma unroll
                for (int j = 0; j < 8; j++)
                    acc[i][j] = fmaf(a[i], b[j], acc[i][j]);
        }
        __syncthreads();
    }

    const float* br = bias + n0 + (tx << 3);
    float bb[8];
    #pragma unroll
    for (int j = 0; j < 8; j++) bb[j] = br[j];

    #pragma unroll
    for (int i = 0; i < 8; i++) {
        int row = m0 + (ty << 3) + i;
        float* Cr = C + (size_t)row * N + n0 + (tx << 3);
        float4 o0, o1;
        o0.x = acc[i][0] + bb[0]; o0.y = acc[i][1] + bb[1];
        o0.z = acc[i][2] + bb[2]; o0.w = acc[i][3] + bb[3];
        o1.x = acc[i][4] + bb[4]; o1.y = acc[i][5] + bb[5];
        o1.z = acc[i][6] + bb[6]; o1.w = acc[i][7] + bb[7];
        *(float4*)(Cr)     = o0;
        *(float4*)(Cr + 4) = o1;
    }
}

// ---------------------------------------------------------------------------
// Kernel 2: feature map.  For each (b,h):
//   Z[s,r] = sum_d Q[b,s,h*HD+d] * RF[h,d,r]
//   OUT[bh,s,r] = exp(Z[s,r] - 0.5 * ||Q row||^2)
// grid: (R/128, S/128, B*H); 256 threads, 8x8 per thread.
// ---------------------------------------------------------------------------
__global__ void __launch_bounds__(256)
feature_kernel(const float* __restrict__ QK, const float* __restrict__ RF,
               float* __restrict__ OUT)
{
    __shared__ float As[8][128];
    __shared__ float Bs[8][128];
    __shared__ float rowsq[128];

    const int tid = threadIdx.x;
    const int tx = tid & 15;
    const int ty = tid >> 4;
    const int bh = blockIdx.z;
    const int b  = bh >> 4;
    const int h  = bh & 15;
    const int s0 = blockIdx.y << 7;
    const int r0 = blockIdx.x << 7;

    const float* Ab = QK + ((size_t)b * Sc + s0) * Dc + h * HDc;
    const float* Bb = RF + (size_t)h * HDc * Rc + r0;

    const int lrow = tid >> 1;
    const int lk   = (tid & 1) << 2;
    const int bkk  = tid >> 5;          // 0..7
    const int bns  = (tid & 31) << 2;   // 0..124

    float acc[8][8];
    #pragma unroll
    for (int i = 0; i < 8; i++)
        #pragma unroll
        for (int j = 0; j < 8; j++) acc[i][j] = 0.0f;
    float rq[8];
    #pragma unroll
    for (int i = 0; i < 8; i++) rq[i] = 0.0f;

    for (int k0 = 0; k0 < HDc; k0 += 8) {
        float4 av = *(const float4*)(Ab + (size_t)lrow * Dc + k0 + lk);
        As[lk + 0][lrow] = av.x; As[lk + 1][lrow] = av.y;
        As[lk + 2][lrow] = av.z; As[lk + 3][lrow] = av.w;
        *(float4*)(&Bs[bkk][bns]) =
            *(const float4*)(Bb + (size_t)(k0 + bkk) * Rc + bns);
        __syncthreads();
        #pragma unroll
        for (int kk = 0; kk < 8; kk++) {
            float a[8], bvals[8];
            *(float4*)(a)         = *(const float4*)(&As[kk][ty << 3]);
            *(float4*)(a + 4)     = *(const float4*)(&As[kk][(ty << 3) + 4]);
            *(float4*)(bvals)     = *(const float4*)(&Bs[kk][tx << 3]);
            *(float4*)(bvals + 4) = *(const float4*)(&Bs[kk][(tx << 3) + 4]);
            #pragma unroll
            for (int i = 0; i < 8; i++)
                #pragma unroll
                for (int j = 0; j < 8; j++)
                    acc[i][j] = fmaf(a[i], bvals[j], acc[i][j]);
            if (tx == 0) {
                #pragma unroll
                for (int i = 0; i < 8; i++) rq[i] = fmaf(a[i], a[i], rq[i]);
            }
        }
        __syncthreads();
    }

    if (tx == 0) {
        #pragma unroll
        for (int i = 0; i < 8; i++) rowsq[(ty << 3) + i] = rq[i];
    }
    __syncthreads();

    const size_t outbase = (size_t)bh * Sc * Rc;
    #pragma unroll
    for (int i = 0; i < 8; i++) {
        int srow = s0 + (ty << 3) + i;
        float hn = 0.5f * rowsq[(ty << 3) + i];
        float* o = OUT + outbase + (size_t)srow * Rc + r0 + (tx << 3);
        float4 o0, o1;
        o0.x = expf(acc[i][0] - hn); o0.y = expf(acc[i][1] - hn);
        o0.z = expf(acc[i][2] - hn); o0.w = expf(acc[i][3] - hn);
        o1.x = expf(acc[i][4] - hn); o1.y = expf(acc[i][5] - hn);
        o1.z = expf(acc[i][6] - hn); o1.w = expf(acc[i][7] - hn);
        *(float4*)(o)     = o0;
        *(float4*)(o + 4) = o1;
    }
}

// ---------------------------------------------------------------------------
// Kernel 3: kv aggregation + ksum.  For each (b,h):
//   KV[r,d]  = sum_s KP[bh,s,r] * V[b,s,h*HD+d]     (r in 256, d in 64)
//   KSUM[r]  = sum_s KP[bh,s,r]
// grid: (R/128, B*H); 256 threads, 8x4 per thread, K chunk = 16.
// ---------------------------------------------------------------------------
__global__ void __launch_bounds__(256)
kv_kernel(const float* __restrict__ KP, const float* __restrict__ V,
          float* __restrict__ KV, float* __restrict__ KSUM)
{
    __shared__ float Ks[16][128];
    __shared__ float Vs[16][64];

    const int tid = threadIdx.x;
    const int tx = tid & 15;
    const int ty = tid >> 4;
    const int bh = blockIdx.y;
    const int b  = bh >> 4;
    const int h  = bh & 15;
    const int rbase = blockIdx.x << 7;

    const float* Kpb = KP + (size_t)bh * Sc * Rc;
    const float* Vb  = V + (size_t)b * Sc * Dc + h * HDc;

    float acc[8][4];
    #pragma unroll
    for (int i = 0; i < 8; i++)
        #pragma unroll
        for (int j = 0; j < 4; j++) acc[i][j] = 0.0f;
    float ks[8];
    #pragma unroll
    for (int i = 0; i < 8; i++) ks[i] = 0.0f;

    const int vrow = tid >> 4, vdseg = (tid & 15) << 2;

    for (int s0 = 0; s0 < Sc; s0 += 16) {
        #pragma unroll
        for (int L = 0; L < 2; L++) {
            int f = tid + (L << 8);       // 0..511
            int si = f >> 5;              // 0..15
            int rseg = (f & 31) << 2;     // 0..124
            *(float4*)(&Ks[si][rseg]) =
                *(const float4*)(Kpb + (size_t)(s0 + si) * Rc + rbase + rseg);
        }
        *(float4*)(&Vs[vrow][vdseg]) =
            *(const float4*)(Vb + (size_t)(s0 + vrow) * Dc + vdseg);
        __syncthreads();
        #pragma unroll
        for (int kk = 0; kk < 16; kk++) {
            float a[8], bv[4];
            *(float4*)(a)     = *(const float4*)(&Ks[kk][ty << 3]);
            *(float4*)(a + 4) = *(const float4*)(&Ks[kk][(ty << 3) + 4]);
            *(float4*)(bv)    = *(const float4*)(&Vs[kk][tx << 2]);
            #pragma unroll
            for (int i = 0; i < 8; i++)
                #pragma unroll
                for (int j = 0; j < 4; j++)
                    acc[i][j] = fmaf(a[i], bv[j], acc[i][j]);
            if (tx == 0) {
                #pragma unroll
                for (int i = 0; i < 8; i++) ks[i] += a[i];
            }
        }
        __syncthreads();
    }

    #pragma unroll
    for (int i = 0; i < 8; i++) {
        int r = rbase + (ty << 3) + i;
        float* o = KV + ((size_t)bh * Rc + r) * HDc + (tx << 2);
        *(float4*)o = make_float4(acc[i][0], acc[i][1], acc[i][2], acc[i][3]);
    }
    if (tx == 0) {
        #pragma unroll
        for (int i = 0; i < 8; i++)
            KSUM[(size_t)bh * Rc + rbase + (ty << 3) + i] = ks[i];
    }
}

// ---------------------------------------------------------------------------
// Kernel 4: attention readout.  For each (b,h):
//   O[s,d]  = (sum_r QP[bh,s,r] * KV[bh,r,d]) / (sum_r QP[bh,s,r]*KSUM[bh,r] + 1e-6)
// written back in [b,s,D] layout (head h at column offset h*HD).
// grid: (S/128, B*H); 256 threads, 8x4 per thread, K chunk = 16.
// ---------------------------------------------------------------------------
__global__ void __launch_bounds__(256)
attn_kernel(const float* __restrict__ QP, const float* __restrict__ KV,
            const float* __restrict__ KSUM, float* __restrict__ OUT)
{
    __shared__ float As[16][128];
    __shared__ float Bs[16][64];
    __shared__ float kss[16];
    __shared__ float nrm[128];

    const int tid = threadIdx.x;
    const int tx = tid & 15;
    const int ty = tid >> 4;
    const int bh = blockIdx.y;
    const int b  = bh >> 4;
    const int h  = bh & 15;
    const int s0 = blockIdx.x << 7;

    const float* Qb  = QP + (size_t)bh * Sc * Rc + (size_t)s0 * Rc;
    const float* KVb = KV + (size_t)bh * Rc * HDc;
    const float* KSb = KSUM + (size_t)bh * Rc;

    float acc[8][4];
    #pragma unroll
    for (int i = 0; i < 8; i++)
        #pragma unroll
        for (int j = 0; j < 4; j++) acc[i][j] = 0.0f;
    float nacc[8];
    #pragma unroll
    for (int i = 0; i < 8; i++) nacc[i] = 0.0f;

    const int bri = tid >> 4, bdseg = (tid & 15) << 2;

    for (int r0 = 0; r0 < Rc; r0 += 16) {
        #pragma unroll
        for (int L = 0; L < 2; L++) {
            int f = tid + (L << 8);     // 0..511
            int srow = f >> 2;          // 0..127
            int rseg = (f & 3) << 2;    // 0,4,8,12
            float4 av = *(const float4*)(Qb + (size_t)srow * Rc + r0 + rseg);
            As[rseg + 0][srow] = av.x; As[rseg + 1][srow] = av.y;
            As[rseg + 2][srow] = av.z; As[rseg + 3][srow] = av.w;
        }
        *(float4*)(&Bs[bri][bdseg]) =
            *(const float4*)(KVb + (size_t)(r0 + bri) * HDc + bdseg);
        if (tid < 16) kss[tid] = KSb[r0 + tid];
        __syncthreads();
        #pragma unroll
        for (int kk = 0; kk < 16; kk++) {
            float a[8], bv[4];
            *(float4*)(a)     = *(const float4*)(&As[kk][ty << 3]);
            *(float4*)(a + 4) = *(const float4*)(&As[kk][(ty << 3) + 4]);
            *(float4*)(bv)    = *(const float4*)(&Bs[kk][tx << 2]);
            #pragma unroll
            for (int i = 0; i < 8; i++)
                #pragma unroll
                for (int j = 0; j < 4; j++)
                    acc[i][j] = fmaf(a[i], bv[j], acc[i][j]);
            if (tx == 0) {
                float kvv = kss[kk];
                #pragma unroll
                for (int i = 0; i < 8; i++) nacc[i] = fmaf(a[i], kvv, nacc[i]);
            }
        }
        __syncthreads();
    }

    if (tx == 0) {
        #pragma unroll
        for (int i = 0; i < 8; i++) nrm[(ty << 3) + i] = nacc[i];
    }
    __syncthreads();

    #pragma unroll
    for (int i = 0; i < 8; i++) {
        int sg = s0 + (ty << 3) + i;
        float inv = 1.0f / (nrm[(ty << 3) + i] + 1e-6f);
        float* o = OUT + ((size_t)b * Sc + sg) * Dc + h * HDc + (tx << 2);
        *(float4*)o = make_float4(acc[i][0] * inv, acc[i][1] * inv,
                                  acc[i][2] * inv, acc[i][3] * inv);
    }
}

// ---------------------------------------------------------------------------
// Launch
// ---------------------------------------------------------------------------
extern "C" void kernel_launch(void* const* d_in, const int* in_sizes, int n_in,
                              void* d_out, int out_size)
{
    (void)in_sizes; (void)n_in; (void)out_size;
    const float* x  = (const float*)d_in[0];
    const float* wq = (const float*)d_in[1];
    const float* bq = (const float*)d_in[2];
    const float* wk = (const float*)d_in[3];
    const float* bk = (const float*)d_in[4];
    const float* wv = (const float*)d_in[5];
    const float* bv = (const float*)d_in[6];
    const float* wo = (const float*)d_in[7];
    const float* bo = (const float*)d_in[8];
    const float* rf = (const float*)d_in[9];
    float* out = (float*)d_out;

    float *pq, *pk, *pv, *pqp, *pkp, *pkv, *pks, *pat;
    cudaGetSymbolAddress((void**)&pq,  g_q);
    cudaGetSymbolAddress((void**)&pk,  g_k);
    cudaGetSymbolAddress((void**)&pv,  g_v);
    cudaGetSymbolAddress((void**)&pqp, g_qp);
    cudaGetSymbolAddress((void**)&pkp, g_kp);
    cudaGetSymbolAddress((void**)&pkv, g_kvagg);
    cudaGetSymbolAddress((void**)&pks, g_ksum);
    cudaGetSymbolAddress((void**)&pat, g_attn);

    dim3 gproj(Dc / 128, Mtot / 128);           // (8, 128)
    sgemm_nt_bias<<<gproj, 256>>>(x, wq, bq, pq, Mtot, Dc, Dc);
    sgemm_nt_bias<<<gproj, 256>>>(x, wk, bk, pk, Mtot, Dc, Dc);
    sgemm_nt_bias<<<gproj, 256>>>(x, wv, bv, pv, Mtot, Dc, Dc);

    dim3 gfeat(Rc / 128, Sc / 128, Bc * Hc);    // (2, 32, 64)
    feature_kernel<<<gfeat, 256>>>(pq, rf, pqp);
    feature_kernel<<<gfeat, 256>>>(pk, rf, pkp);

    dim3 gkv(Rc / 128, Bc * Hc);                // (2, 64)
    kv_kernel<<<gkv, 256>>>(pkp, pv, pkv, pks);

    dim3 gat(Sc / 128, Bc * Hc);                // (32, 64)
    attn_kernel<<<gat, 256>>>(pqp, pkv, pks, pat);

    sgemm_nt_bias<<<gproj, 256>>>(pat, wo, bo, out, Mtot, Dc, Dc);
}

// round 2
// speedup vs baseline: 1.0004x; 1.0004x over previous
#include <cuda_runtime.h>
#include <math.h>

// Problem constants
#define Bc 4
#define Sc 4096
#define Dc 1024
#define Hc 16
#define Rc 256
#define HDc 64
#define Mtot (Bc * Sc)          // 16384 rows for the big GEMMs

// ---------------------------------------------------------------------------
// Scratch (device globals -- no runtime allocation allowed)
// ---------------------------------------------------------------------------
__device__ float g_q[(size_t)Mtot * Dc];                 // 64 MB  [b,s,D]
__device__ float g_k[(size_t)Mtot * Dc];                 // 64 MB
__device__ float g_v[(size_t)Mtot * Dc];                 // 64 MB
__device__ float g_qp[(size_t)Bc * Hc * Sc * Rc];        // 64 MB  [bh,s,r]
__device__ float g_kp[(size_t)Bc * Hc * Sc * Rc];        // 64 MB
__device__ float g_kvagg[(size_t)Bc * Hc * Rc * HDc];    // 4 MB   [bh,r,d]
__device__ float g_ksum[(size_t)Bc * Hc * Rc];           // 64 KB  [bh,r]
__device__ float g_attn[(size_t)Mtot * Dc];              // 64 MB  [b,s,D]

// ---------------------------------------------------------------------------
// Kernel 1: C[m,n] = sum_k A[m,k] * B[n,k] + bias[n]      (NT GEMM, fp32)
// A:[M,K] row-major, B:[N,K] row-major. M%128==0, N%128==0, K%8==0 assumed.
// 128x128 block tile, 8x8 per thread, BK=8.
// ---------------------------------------------------------------------------
__global__ void __launch_bounds__(256)
sgemm_nt_bias(const float* __restrict__ A, const float* __restrict__ B,
              const float* __restrict__ bias, float* __restrict__ C,
              int M, int N, int K)
{
    __shared__ float As[8][128];
    __shared__ float Bs[8][128];

    const int tid = threadIdx.x;
    const int tx = tid & 15;          // column group (8 cols)
    const int ty = tid >> 4;          // row group (8 rows)
    const int m0 = blockIdx.y << 7;
    const int n0 = blockIdx.x << 7;

    const int lrow = tid >> 1;        // 0..127
    const int lk   = (tid & 1) << 2;  // 0 or 4
    const float* Ag = A + (size_t)(m0 + lrow) * K + lk;
    const float* Bg = B + (size_t)(n0 + lrow) * K + lk;

    float acc[8][8];
    #pragma unroll
    for (int i = 0; i < 8; i++)
        #pragma unroll
        for (int j = 0; j < 8; j++) acc[i][j] = 0.0f;

    for (int k0 = 0; k0 < K; k0 += 8) {
        float4 av = *(const float4*)(Ag + k0);
        float4 bv = *(const float4*)(Bg + k0);
        As[lk + 0][lrow] = av.x; As[lk + 1][lrow] = av.y;
        As[lk + 2][lrow] = av.z; As[lk + 3][lrow] = av.w;
        Bs[lk + 0][lrow] = bv.x; Bs[lk + 1][lrow] = bv.y;
        Bs[lk + 2][lrow] = bv.z; Bs[lk + 3][lrow] = bv.w;
        __syncthreads();
        #pragma unroll
        for (int kk = 0; kk < 8; kk++) {
            float a[8], b[8];
            *(float4*)(a)     = *(const float4*)(&As[kk][ty << 3]);
            *(float4*)(a + 4) = *(const float4*)(&As[kk][(ty << 3) + 4]);
            *(float4*)(b)     = *(const float4*)(&Bs[kk][tx << 3]);
            *(float4*)(b + 4) = *(const float4*)(&Bs[kk][(tx << 3) + 4]);
            #pragma unroll
            for (int i = 0; i < 8; i++)
                #pragma unroll
                for (int j = 0; j < 8; j++)
                    acc[i][j] = fmaf(a[i], b[j], acc[i][j]);
        }
        __syncthreads();
    }

    const float* br = bias + n0 + (tx << 3);
    float bb[8];
    #pragma unroll
    for (int j = 0; j < 8; j++) bb[j] = br[j];

    #pragma unroll
    for (int i = 0; i < 8; i++) {
        int row = m0 + (ty << 3) + i;
        float* Cr = C + (size_t)row * N + n0 + (tx << 3);
        float4 o0, o1;
        o0.x = acc[i][0] + bb[0]; o0.y = acc[i][1] + bb[1];
        o0.z = acc[i][2] + bb[2]; o0.w = acc[i][3] + bb[3];
        o1.x = acc[i][4] + bb[4]; o1.y = acc[i][5] + bb[5];
        o1.z = acc[i][6] + bb[6]; o1.w = acc[i][7] + bb[7];
        *(float4*)(Cr)     = o0;
        *(float4*)(Cr + 4) = o1;
    }
}

// ---------------------------------------------------------------------------
// Kernel 2: feature map.  For each (b,h):
//   Z[s,r] = sum_d Q[b,s,h*HD+d] * RF[h,d,r]
//   OUT[bh,s,r] = exp(Z[s,r] - 0.5 * ||Q row||^2)
// grid: (R/128, S/128, B*H); 256 threads, 8x8 per thread.
// ---------------------------------------------------------------------------
__global__ void __launch_bounds__(256)
feature_kernel(const float* __restrict__ QK, const float* __restrict__ RF,
               float* __restrict__ OUT)
{
    __shared__ float As[8][128];
    __shared__ float Bs[8][128];
    __shared__ float rowsq[128];

    const int tid = threadIdx.x;
    const int tx = tid & 15;
    const int ty = tid >> 4;
    const int bh = blockIdx.z;
    const int b  = bh >> 4;
    const int h  = bh & 15;
    const int s0 = blockIdx.y << 7;
    const int r0 = blockIdx.x << 7;

    const float* Ab = QK + ((size_t)b * Sc + s0) * Dc + h * HDc;
    const float* Bb = RF + (size_t)h * HDc * Rc + r0;

    const int lrow = tid >> 1;
    const int lk   = (tid & 1) << 2;
    const int bkk  = tid >> 5;          // 0..7
    const int bns  = (tid & 31) << 2;   // 0..124

    float acc[8][8];
    #pragma unroll
    for (int i = 0; i < 8; i++)
        #pragma unroll
        for (int j = 0; j < 8; j++) acc[i][j] = 0.0f;
    float rq[8];
    #pragma unroll
    for (int i = 0; i < 8; i++) rq[i] = 0.0f;

    for (int k0 = 0; k0 < HDc; k0 += 8) {
        float4 av = *(const float4*)(Ab + (size_t)lrow * Dc + k0 + lk);
        As[lk + 0][lrow] = av.x; As[lk + 1][lrow] = av.y;
        As[lk + 2][lrow] = av.z; As[lk + 3][lrow] = av.w;
        *(float4*)(&Bs[bkk][bns]) =
            *(const float4*)(Bb + (size_t)(k0 + bkk) * Rc + bns);
        __syncthreads();
        #pragma unroll
        for (int kk = 0; kk < 8; kk++) {
            float a[8], bvals[8];
            *(float4*)(a)         = *(const float4*)(&As[kk][ty << 3]);
            *(float4*)(a + 4)     = *(const float4*)(&As[kk][(ty << 3) + 4]);
            *(float4*)(bvals)     = *(const float4*)(&Bs[kk][tx << 3]);
            *(float4*)(bvals + 4) = *(const float4*)(&Bs[kk][(tx << 3) + 4]);
            #pragma unroll
            for (int i = 0; i < 8; i++)
                #pragma unroll
                for (int j = 0; j < 8; j++)
                    acc[i][j] = fmaf(a[i], bvals[j], acc[i][j]);
            if (tx == 0) {
                #pragma unroll
                for (int i = 0; i < 8; i++) rq[i] = fmaf(a[i], a[i], rq[i]);
            }
        }
        __syncthreads();
    }

    if (tx == 0) {
        #pragma unroll
        for (int i = 0; i < 8; i++) rowsq[(ty << 3) + i] = rq[i];
    }
    __syncthreads();

    const size_t outbase = (size_t)bh * Sc * Rc;
    #pragma unroll
    for (int i = 0; i < 8; i++) {
        int srow = s0 + (ty << 3) + i;
        float hn = 0.5f * rowsq[(ty << 3) + i];
        float* o = OUT + outbase + (size_t)srow * Rc + r0 + (tx << 3);
        float4 o0, o1;
        o0.x = expf(acc[i][0] - hn); o0.y = expf(acc[i][1] - hn);
        o0.z = expf(acc[i][2] - hn); o0.w = expf(acc[i][3] - hn);
        o1.x = expf(acc[i][4] - hn); o1.y = expf(acc[i][5] - hn);
        o1.z = expf(acc[i][6] - hn); o1.w = expf(acc[i][7] - hn);
        *(float4*)(o)     = o0;
        *(float4*)(o + 4) = o1;
    }
}

// ---------------------------------------------------------------------------
// Kernel 3: kv aggregation + ksum.  For each (b,h):
//   KV[r,d]  = sum_s KP[bh,s,r] * V[b,s,h*HD+d]     (r in 256, d in 64)
//   KSUM[r]  = sum_s KP[bh,s,r]
// grid: (R/128, B*H); 256 threads, 8x4 per thread, K chunk = 16.
// ---------------------------------------------------------------------------
__global__ void __launch_bounds__(256)
kv_kernel(const float* __restrict__ KP, const float* __restrict__ V,
          float* __restrict__ KV, float* __restrict__ KSUM)
{
    __shared__ float Ks[16][128];
    __shared__ float Vs[16][64];

    const int tid = threadIdx.x;
    const int tx = tid & 15;
    const int ty = tid >> 4;
    const int bh = blockIdx.y;
    const int b  = bh >> 4;
    const int h  = bh & 15;
    const int rbase = blockIdx.x << 7;

    const float* Kpb = KP + (size_t)bh * Sc * Rc;
    const float* Vb  = V + (size_t)b * Sc * Dc + h * HDc;

    float acc[8][4];
    #pragma unroll
    for (int i = 0; i < 8; i++)
        #pragma unroll
        for (int j = 0; j < 4; j++) acc[i][j] = 0.0f;
    float ks[8];
    #pragma unroll
    for (int i = 0; i < 8; i++) ks[i] = 0.0f;

    const int vrow = tid >> 4, vdseg = (tid & 15) << 2;

    for (int s0 = 0; s0 < Sc; s0 += 16) {
        #pragma unroll
        for (int L = 0; L < 2; L++) {
            int f = tid + (L << 8);       // 0..511
            int si = f >> 5;              // 0..15
            int rseg = (f & 31) << 2;     // 0..124
            *(float4*)(&Ks[si][rseg]) =
                *(const float4*)(Kpb + (size_t)(s0 + si) * Rc + rbase + rseg);
        }
        *(float4*)(&Vs[vrow][vdseg]) =
            *(const float4*)(Vb + (size_t)(s0 + vrow) * Dc + vdseg);
        __syncthreads();
        #pragma unroll
        for (int kk = 0; kk < 16; kk++) {
            float a[8], bv[4];
            *(float4*)(a)     = *(const float4*)(&Ks[kk][ty << 3]);
            *(float4*)(a + 4) = *(const float4*)(&Ks[kk][(ty << 3) + 4]);
            *(float4*)(bv)    = *(const float4*)(&Vs[kk][tx << 2]);
            #pragma unroll
            for (int i = 0; i < 8; i++)
                #pragma unroll
                for (int j = 0; j < 4; j++)
                    acc[i][j] = fmaf(a[i], bv[j], acc[i][j]);
            if (tx == 0) {
                #pragma unroll
                for (int i = 0; i < 8; i++) ks[i] += a[i];
            }
        }
        __syncthreads();
    }

    #pragma unroll
    for (int i = 0; i < 8; i++) {
        int r = rbase + (ty << 3) + i;
        float* o = KV + ((size_t)bh * Rc + r) * HDc + (tx << 2);
        *(float4*)o = make_float4(acc[i][0], acc[i][1], acc[i][2], acc[i][3]);
    }
    if (tx == 0) {
        #pragma unroll
        for (int i = 0; i < 8; i++)
            KSUM[(size_t)bh * Rc + rbase + (ty << 3) + i] = ks[i];
    }
}

// ---------------------------------------------------------------------------
// Kernel 4: attention readout.  For each (b,h):
//   O[s,d]  = (sum_r QP[bh,s,r] * KV[bh,r,d]) / (sum_r QP[bh,s,r]*KSUM[bh,r] + 1e-6)
// written back in [b,s,D] layout (head h at column offset h*HD).
// grid: (S/128, B*H); 256 threads, 8x4 per thread, K chunk = 16.
// ---------------------------------------------------------------------------
__global__ void __launch_bounds__(256)
attn_kernel(const float* __restrict__ QP, const float* __restrict__ KV,
            const float* __restrict__ KSUM, float* __restrict__ OUT)
{
    __shared__ float As[16][128];
    __shared__ float Bs[16][64];
    __shared__ float kss[16];
    __shared__ float nrm[128];

    const int tid = threadIdx.x;
    const int tx = tid & 15;
    const int ty = tid >> 4;
    const int bh = blockIdx.y;
    const int b  = bh >> 4;
    const int h  = bh & 15;
    const int s0 = blockIdx.x << 7;

    const float* Qb  = QP + (size_t)bh * Sc * Rc + (size_t)s0 * Rc;
    const float* KVb = KV + (size_t)bh * Rc * HDc;
    const float* KSb = KSUM + (size_t)bh * Rc;

    float acc[8][4];
    #pragma unroll
    for (int i = 0; i < 8; i++)
        #pragma unroll
        for (int j = 0; j < 4; j++) acc[i][j] = 0.0f;
    float nacc[8];
    #pragma unroll
    for (int i = 0; i < 8; i++) nacc[i] = 0.0f;

    const int bri = tid >> 4, bdseg = (tid & 15) << 2;

    for (int r0 = 0; r0 < Rc; r0 += 16) {
        #pragma unroll
        for (int L = 0; L < 2; L++) {
            int f = tid + (L << 8);     // 0..511
            int srow = f >> 2;          // 0..127
            int rseg = (f & 3) << 2;    // 0,4,8,12
            float4 av = *(const float4*)(Qb + (size_t)srow * Rc + r0 + rseg);
            As[rseg + 0][srow] = av.x; As[rseg + 1][srow] = av.y;
            As[rseg + 2][srow] = av.z; As[rseg + 3][srow] = av.w;
        }
        *(float4*)(&Bs[bri][bdseg]) =
            *(const float4*)(KVb + (size_t)(r0 + bri) * HDc + bdseg);
        if (tid < 16) kss[tid] = KSb[r0 + tid];
        __syncthreads();
        #pragma unroll
        for (int kk = 0; kk < 16; kk++) {
            float a[8], bv[4];
            *(float4*)(a)     = *(const float4*)(&As[kk][ty << 3]);
            *(float4*)(a + 4) = *(const float4*)(&As[kk][(ty << 3) + 4]);
            *(float4*)(bv)    = *(const float4*)(&Bs[kk][tx << 2]);
            #pragma unroll
            for (int i = 0; i < 8; i++)
                #pragma unroll
                for (int j = 0; j < 4; j++)
                    acc[i][j] = fmaf(a[i], bv[j], acc[i][j]);
            if (tx == 0) {
                float kvv = kss[kk];
                #pragma unroll
                for (int i = 0; i < 8; i++) nacc[i] = fmaf(a[i], kvv, nacc[i]);
            }
        }
        __syncthreads();
    }

    if (tx == 0) {
        #pragma unroll
        for (int i = 0; i < 8; i++) nrm[(ty << 3) + i] = nacc[i];
    }
    __syncthreads();

    #pragma unroll
    for (int i = 0; i < 8; i++) {
        int sg = s0 + (ty << 3) + i;
        float inv = 1.0f / (nrm[(ty << 3) + i] + 1e-6f);
        float* o = OUT + ((size_t)b * Sc + sg) * Dc + h * HDc + (tx << 2);
        *(float4*)o = make_float4(acc[i][0] * inv, acc[i][1] * inv,
                                  acc[i][2] * inv, acc[i][3] * inv);
    }
}

// ---------------------------------------------------------------------------
// Launch
// ---------------------------------------------------------------------------
extern "C" void kernel_launch(void* const* d_in, const int* in_sizes, int n_in,
                              void* d_out, int out_size)
{
    (void)in_sizes; (void)n_in; (void)out_size;
    const float* x  = (const float*)d_in[0];
    const float* wq = (const float*)d_in[1];
    const float* bq = (const float*)d_in[2];
    const float* wk = (const float*)d_in[3];
    const float* bk = (const float*)d_in[4];
    const float* wv = (const float*)d_in[5];
    const float* bv = (const float*)d_in[6];
    const float* wo = (const float*)d_in[7];
    const float* bo = (const float*)d_in[8];
    const float* rf = (const float*)d_in[9];
    float* out = (float*)d_out;

    float *pq, *pk, *pv, *pqp, *pkp, *pkv, *pks, *pat;
    cudaGetSymbolAddress((void**)&pq,  g_q);
    cudaGetSymbolAddress((void**)&pk,  g_k);
    cudaGetSymbolAddress((void**)&pv,  g_v);
    cudaGetSymbolAddress((void**)&pqp, g_qp);
    cudaGetSymbolAddress((void**)&pkp, g_kp);
    cudaGetSymbolAddress((void**)&pkv, g_kvagg);
    cudaGetSymbolAddress((void**)&pks, g_ksum);
    cudaGetSymbolAddress((void**)&pat, g_attn);

    dim3 gproj(Dc / 128, Mtot / 128);           // (8, 128)
    sgemm_nt_bias<<<gproj, 256>>>(x, wq, bq, pq, Mtot, Dc, Dc);
    sgemm_nt_bias<<<gproj, 256>>>(x, wk, bk, pk, Mtot, Dc, Dc);
    sgemm_nt_bias<<<gproj, 256>>>(x, wv, bv, pv, Mtot, Dc, Dc);

    dim3 gfeat(Rc / 128, Sc / 128, Bc * Hc);    // (2, 32, 64)
    feature_kernel<<<gfeat, 256>>>(pq, rf, pqp);
    feature_kernel<<<gfeat, 256>>>(pk, rf, pkp);

    dim3 gkv(Rc / 128, Bc * Hc);                // (2, 64)
    kv_kernel<<<gkv, 256>>>(pkp, pv, pkv, pks);

    dim3 gat(Sc / 128, Bc * Hc);                // (32, 64)
    attn_kernel<<<gat, 256>>>(pqp, pkv, pks, pat);

    sgemm_nt_bias<<<gproj, 256>>>(pat, wo, bo, out, Mtot, Dc, Dc);
}

// round 4
// speedup vs baseline: 1.1840x; 1.1835x over previous
#include <cuda_runtime.h>
#include <cstdint>
#include <math.h>

#define Bc 4
#define Sc 4096
#define Dc 1024
#define Hc 16
#define Rc 256
#define HDc 64
#define Mtot (Bc * Sc)
#define BK 32

// ---------------- scratch (device globals) ----------------
__device__ float2 g_xs[(size_t)Mtot * Dc];
__device__ float2 g_wqs[(size_t)Dc * Dc];
__device__ float2 g_wks[(size_t)Dc * Dc];
__device__ float2 g_wvs[(size_t)Dc * Dc];
__device__ float2 g_wos[(size_t)Dc * Dc];
__device__ float2 g_rfs[(size_t)Hc * Rc * HDc];
__device__ float2 g_qs[(size_t)Mtot * Dc];
__device__ float2 g_ks[(size_t)Mtot * Dc];
__device__ float  g_v[(size_t)Mtot * Dc];
__device__ float  g_nq[(size_t)Bc * Hc * Sc];
__device__ float  g_nk[(size_t)Bc * Hc * Sc];
__device__ float2 g_qps[(size_t)Bc * Hc * Sc * Rc];
__device__ float  g_kp[(size_t)Bc * Hc * Sc * Rc];
__device__ float  g_kvp[(size_t)8 * Bc * Hc * HDc * Rc];
__device__ float  g_ksp[(size_t)8 * Bc * Hc * Rc];
__device__ float2 g_kvts[(size_t)Bc * Hc * HDc * Rc];
__device__ float  g_ksum[(size_t)Bc * Hc * Rc];
__device__ float2 g_ats[(size_t)Mtot * Dc];

// ---------------- helpers ----------------
__device__ __forceinline__ uint32_t smem_u32(const void* p) {
    uint32_t a;
    asm("{ .reg .u64 t; cvta.to.shared.u64 t, %1; cvt.u32.u64 %0, t; }" : "=r"(a) : "l"(p));
    return a;
}
__device__ __forceinline__ float tf32h(float a) {
    uint32_t u;
    asm("cvt.rna.tf32.f32 %0, %1;" : "=r"(u) : "f"(a));
    return __uint_as_float(u);
}
__device__ __forceinline__ void cpa16(uint32_t dst, const void* src) {
    asm volatile("cp.async.cg.shared.global [%0], [%1], 16;"
                 :: "r"(dst), "l"(__cvta_generic_to_global(src)) : "memory");
}
__device__ __forceinline__ void mma_tf32(float* c, const uint32_t* A, const uint32_t* B) {
    asm volatile(
        "mma.sync.aligned.m16n8k8.row.col.f32.tf32.tf32.f32 "
        "{%0,%1,%2,%3}, {%4,%5,%6,%7}, {%8,%9}, {%0,%1,%2,%3};"
        : "+f"(c[0]), "+f"(c[1]), "+f"(c[2]), "+f"(c[3])
        : "r"(A[0]), "r"(A[1]), "r"(A[2]), "r"(A[3]), "r"(B[0]), "r"(B[1]));
}

// ---------------- split / transpose prep ----------------
__global__ void split_kernel(const float4* __restrict__ src, float2* __restrict__ dst, int n4)
{
    for (int i = blockIdx.x * blockDim.x + threadIdx.x; i < n4; i += gridDim.x * blockDim.x) {
        float4 a = src[i];
        float2* o = dst + (size_t)i * 4;
        float h;
        h = tf32h(a.x); o[0] = make_float2(h, tf32h(a.x - h));
        h = tf32h(a.y); o[1] = make_float2(h, tf32h(a.y - h));
        h = tf32h(a.z); o[2] = make_float2(h, tf32h(a.z - h));
        h = tf32h(a.w); o[3] = make_float2(h, tf32h(a.w - h));
    }
}
// rf[h][d][r] -> rfs[h][r][d] (split)
__global__ void rft_kernel(const float* __restrict__ rf, float2* __restrict__ out)
{
    int idx = blockIdx.x * blockDim.x + threadIdx.x;
    if (idx >= Hc * Rc * HDc) return;
    int d = idx & 63, r = (idx >> 6) & 255, h = idx >> 14;
    float a = rf[((size_t)(h * HDc + d)) * Rc + r];
    float hv = tf32h(a);
    out[idx] = make_float2(hv, tf32h(a - hv));
}
// per-(row, head) squared norm of q (from split storage)
__global__ void qnorm_kernel(const float2* __restrict__ qs, float* __restrict__ nrm)
{
    int gw = blockIdx.x * 8 + (threadIdx.x >> 5);
    int lane = threadIdx.x & 31;
    int row = gw >> 4, head = gw & 15;
    const float2* p = qs + (size_t)row * Dc + head * HDc;
    float2 v1 = p[lane], v2 = p[lane + 32];
    float a = v1.x + v1.y, b = v2.x + v2.y;
    float s = a * a + b * b;
    #pragma unroll
    for (int o = 16; o; o >>= 1) s += __shfl_xor_sync(0xffffffffu, s, o);
    if (lane == 0) {
        int bb = row >> 12, srow = row & 4095;
        nrm[((size_t)(bb * 16 + head)) * Sc + srow] = s;
    }
}

// ---------------- tensor GEMM engine ----------------
// C[128 x NTILE] per CTA, C = A * B^T in fp32 via 3xTF32 mma.sync.
// A, B stored as split float2 {hi, lo}.
// EPI: 0 +bias -> f32 out | 1 +bias -> split out | 2 exp(v-0.5*norm) -> split
//      3 exp(v-0.5*norm) -> f32 | 4 normalize by in-loop (A . ksum) -> split
struct TGP {
    const float2 *a, *b;
    long long a_ob, a_oh, b_ob, b_oh, o_ob, o_oh;
    int a_st, b_st, o_st, K;
    const float *bias, *norm, *ksum;
    float*  o0;   // plain out (EPI 0,3)
    float2* o0s;  // split out (EPI 1,2,4)
};

template<int NTILE, int EPI>
__global__ void __launch_bounds__(256, 1) tgemm(TGP p)
{
    extern __shared__ float2 smf2[];
    const int tid = threadIdx.x, lane = tid & 31, wid = tid >> 5;
    const int z = blockIdx.z;
    const int m0 = blockIdx.y << 7, n0 = blockIdx.x * NTILE;

    constexpr int MT = (NTILE == 128) ? 4 : 2;
    const int wm0 = (NTILE == 128) ? ((wid & 1) << 6) : ((wid & 3) << 5);
    const int wn0 = (NTILE == 128) ? ((wid >> 1) << 5) : ((wid >> 2) << 5);

    constexpr int ASF = 128 * 36;
    constexpr int BSF = NTILE * 36;
    float2* const A0 = smf2;
    float2* const B0 = smf2 + ASF;
    float2* const A1 = smf2 + ASF + BSF;
    float2* const B1 = smf2 + 2 * ASF + BSF;
    float* const ksums = (float*)(smf2 + 2 * (ASF + BSF));
    float* const snorm = ksums + 256;

    const size_t aoff = (size_t)p.a_ob * (z >> 4) + (size_t)p.a_oh * (z & 15);
    const size_t boff = (size_t)p.b_ob * (z >> 4) + (size_t)p.b_oh * (z & 15);
    const size_t ooff = (size_t)p.o_ob * (z >> 4) + (size_t)p.o_oh * (z & 15);

    if (EPI == 4) ksums[tid] = p.ksum[(size_t)z * Rc + tid];

    const int steps = p.K / BK;

    auto issue = [&](int step, int buf) {
        const size_t k0 = (size_t)step * BK;
        float2* Ad = buf ? A1 : A0;
        float2* Bd = buf ? B1 : B0;
        const float2* Ag = p.a + aoff + k0;
        const float2* Bg = p.b + boff + k0;
        for (int j = tid; j < 128 * 16; j += 256) {
            int row = j >> 4, seg = j & 15;
            cpa16(smem_u32(Ad + row * 36 + seg * 2),
                  Ag + (size_t)(m0 + row) * p.a_st + seg * 2);
        }
        for (int j = tid; j < NTILE * 16; j += 256) {
            int row = j >> 4, seg = j & 15;
            cpa16(smem_u32(Bd + row * 36 + seg * 2),
                  Bg + (size_t)(n0 + row) * p.b_st + seg * 2);
        }
        asm volatile("cp.async.commit_group;" ::: "memory");
    };

    issue(0, 0);
    if (steps > 1) issue(1, 1);

    float acc[MT][4][4];
    #pragma unroll
    for (int i = 0; i < MT; i++)
        #pragma unroll
        for (int j = 0; j < 4; j++)
            #pragma unroll
            for (int c = 0; c < 4; c++) acc[i][j][c] = 0.0f;
    float nacc = 0.0f;

    for (int i = 0; i < steps; i++) {
        const int buf = i & 1;
        if (i + 1 < steps) asm volatile("cp.async.wait_group 1;" ::: "memory");
        else               asm volatile("cp.async.wait_group 0;" ::: "memory");
        __syncthreads();

        const float2* As = buf ? A1 : A0;
        const float2* Bs = buf ? B1 : B0;

        if (EPI == 4) {
            const int m = tid >> 1, half = tid & 1;
            const float2* ar = As + m * 36 + half * 16;
            const float* kv = ksums + i * BK + half * 16;
            #pragma unroll
            for (int t = 0; t < 16; t++) nacc += (ar[t].x + ar[t].y) * kv[t];
        }

        #pragma unroll
        for (int kk = 0; kk < BK; kk += 8) {
            uint32_t ah[MT][4], al[MT][4];
            const int r = lane >> 2, c = lane & 3;
            #pragma unroll
            for (int im = 0; im < MT; im++) {
                const int mb = wm0 + im * 16;
                float2 e0 = As[(mb + r) * 36 + kk + c];
                float2 e1 = As[(mb + r + 8) * 36 + kk + c];
                float2 e2 = As[(mb + r) * 36 + kk + c + 4];
                float2 e3 = As[(mb + r + 8) * 36 + kk + c + 4];
                ah[im][0] = __float_as_uint(e0.x); al[im][0] = __float_as_uint(e0.y);
                ah[im][1] = __float_as_uint(e1.x); al[im][1] = __float_as_uint(e1.y);
                ah[im][2] = __float_as_uint(e2.x); al[im][2] = __float_as_uint(e2.y);
                ah[im][3] = __float_as_uint(e3.x); al[im][3] = __float_as_uint(e3.y);
            }
            #pragma unroll
            for (int in_ = 0; in_ < 4; in_++) {
                const int nb = wn0 + in_ * 8;
                float2 f0 = Bs[(nb + r) * 36 + kk + c];
                float2 f1 = Bs[(nb + r) * 36 + kk + c + 4];
                uint32_t bhv[2] = { __float_as_uint(f0.x), __float_as_uint(f1.x) };
                uint32_t blv[2] = { __float_as_uint(f0.y), __float_as_uint(f1.y) };
                #pragma unroll
                for (int im = 0; im < MT; im++) {
                    mma_tf32(acc[im][in_], ah[im], bhv);
                    mma_tf32(acc[im][in_], al[im], bhv);
                    mma_tf32(acc[im][in_], ah[im], blv);
                }
            }
        }
        __syncthreads();
        if (i + 2 < steps) issue(i + 2, buf);
    }

    if (EPI == 4) {
        snorm[tid] = nacc;
        __syncthreads();
    }

    // ---------------- epilogue ----------------
    #pragma unroll
    for (int im = 0; im < MT; im++) {
        const int la = wm0 + im * 16 + (lane >> 2);
        const int lb = la + 8;
        const int rA = m0 + la, rB = m0 + lb;
        float hnA = 0.0f, hnB = 0.0f, invA = 1.0f, invB = 1.0f;
        if (EPI == 2 || EPI == 3) {
            hnA = 0.5f * p.norm[(size_t)z * Sc + rA];
            hnB = 0.5f * p.norm[(size_t)z * Sc + rB];
        }
        if (EPI == 4) {
            invA = 1.0f / (snorm[2 * la] + snorm[2 * la + 1] + 1e-6f);
            invB = 1.0f / (snorm[2 * lb] + snorm[2 * lb + 1] + 1e-6f);
        }
        #pragma unroll
        for (int in_ = 0; in_ < 4; in_++) {
            const int n = n0 + wn0 + in_ * 8 + ((lane & 3) << 1);
            float v0 = acc[im][in_][0], v1 = acc[im][in_][1];
            float v2 = acc[im][in_][2], v3 = acc[im][in_][3];
            if (EPI == 0 || EPI == 1) {
                float b0 = __ldg(p.bias + n), b1 = __ldg(p.bias + n + 1);
                v0 += b0; v1 += b1; v2 += b0; v3 += b1;
            } else if (EPI == 2 || EPI == 3) {
                v0 = __expf(v0 - hnA); v1 = __expf(v1 - hnA);
                v2 = __expf(v2 - hnB); v3 = __expf(v3 - hnB);
            } else if (EPI == 4) {
                v0 *= invA; v1 *= invA; v2 *= invB; v3 *= invB;
            }
            if (EPI == 0 || EPI == 3) {
                *(float2*)(p.o0 + ooff + (size_t)rA * p.o_st + n) = make_float2(v0, v1);
                *(float2*)(p.o0 + ooff + (size_t)rB * p.o_st + n) = make_float2(v2, v3);
            } else {
                float2* oA = p.o0s + ooff + (size_t)rA * p.o_st + n;
                float2* oB = p.o0s + ooff + (size_t)rB * p.o_st + n;
                float h0 = tf32h(v0), h1 = tf32h(v1), h2 = tf32h(v2), h3 = tf32h(v3);
                oA[0] = make_float2(h0, tf32h(v0 - h0));
                oA[1] = make_float2(h1, tf32h(v1 - h1));
                oB[0] = make_float2(h2, tf32h(v2 - h2));
                oB[1] = make_float2(h3, tf32h(v3 - h3));
            }
        }
    }
}

// ---------------- SIMT kv aggregation (split-K over 8 s-chunks) ----------------
__global__ void __launch_bounds__(256)
kv_kernel(const float* __restrict__ KP, const float* __restrict__ V,
          float* __restrict__ KVp, float* __restrict__ KSp)
{
    __shared__ float Ks[16][128];
    __shared__ float Vs[16][64];
    const int tid = threadIdx.x, tx = tid & 15, ty = tid >> 4;
    const int bh = blockIdx.z, b = bh >> 4, h = bh & 15;
    const int rbase = blockIdx.x << 7;
    const int sbeg = blockIdx.y << 9;
    const float* Kpb = KP + (size_t)bh * Sc * Rc;
    const float* Vb  = V + (size_t)b * Sc * Dc + h * HDc;

    float acc[8][4];
    #pragma unroll
    for (int i = 0; i < 8; i++)
        #pragma unroll
        for (int j = 0; j < 4; j++) acc[i][j] = 0.0f;
    float ks[8];
    #pragma unroll
    for (int i = 0; i < 8; i++) ks[i] = 0.0f;
    const int vrow = tid >> 4, vdseg = (tid & 15) << 2;

    for (int s0 = sbeg; s0 < sbeg + 512; s0 += 16) {
        #pragma unroll
        for (int L = 0; L < 2; L++) {
            int f = tid + (L << 8), si = f >> 5, rseg = (f & 31) << 2;
            *(float4*)(&Ks[si][rseg]) =
                *(const float4*)(Kpb + (size_t)(s0 + si) * Rc + rbase + rseg);
        }
        *(float4*)(&Vs[vrow][vdseg]) = *(const float4*)(Vb + (size_t)(s0 + vrow) * Dc + vdseg);
        __syncthreads();
        #pragma unroll
        for (int kk = 0; kk < 16; kk++) {
            float a[8], bv[4];
            *(float4*)(a)     = *(const float4*)(&Ks[kk][ty << 3]);
            *(float4*)(a + 4) = *(const float4*)(&Ks[kk][(ty << 3) + 4]);
            *(float4*)(bv)    = *(const float4*)(&Vs[kk][tx << 2]);
            #pragma unroll
            for (int i = 0; i < 8; i++)
                #pragma unroll
                for (int j = 0; j < 4; j++) acc[i][j] = fmaf(a[i], bv[j], acc[i][j]);
            if (tx == 0) {
                #pragma unroll
                for (int i = 0; i < 8; i++) ks[i] += a[i];
            }
        }
        __syncthreads();
    }
    const size_t pb = (size_t)blockIdx.y * 64 + bh;
    float* kvo = KVp + pb * HDc * Rc;
    #pragma unroll
    for (int i = 0; i < 8; i++) {
        int r = rbase + (ty << 3) + i;
        #pragma unroll
        for (int j = 0; j < 4; j++)
            kvo[(size_t)((tx << 2) + j) * Rc + r] = acc[i][j];
    }
    if (tx == 0) {
        #pragma unroll
        for (int i = 0; i < 8; i++)
            KSp[pb * Rc + rbase + (ty << 3) + i] = ks[i];
    }
}

__global__ void kvreduce_kernel(const float* __restrict__ KVp, const float* __restrict__ KSp,
                                float2* __restrict__ KVT, float* __restrict__ KS)
{
    const size_t NELEM = (size_t)64 * HDc * Rc;  // 1M
    size_t idx = (size_t)blockIdx.x * blockDim.x + threadIdx.x;
    if (idx < NELEM) {
        float s = 0.0f;
        #pragma unroll
        for (int c = 0; c < 8; c++) s += KVp[(size_t)c * NELEM + idx];
        float hv = tf32h(s);
        KVT[idx] = make_float2(hv, tf32h(s - hv));
    }
    if (idx < (size_t)64 * Rc) {
        float s = 0.0f;
        #pragma unroll
        for (int c = 0; c < 8; c++) s += KSp[(size_t)c * 64 * Rc + idx];
        KS[idx] = s;
    }
}

// ---------------- launch ----------------
extern "C" void kernel_launch(void* const* d_in, const int* in_sizes, int n_in,
                              void* d_out, int out_size)
{
    (void)in_sizes; (void)n_in; (void)out_size;
    const float* x  = (const float*)d_in[0];
    const float* wq = (const float*)d_in[1];
    const float* bq = (const float*)d_in[2];
    const float* wk = (const float*)d_in[3];
    const float* bk = (const float*)d_in[4];
    const float* wv = (const float*)d_in[5];
    const float* bv = (const float*)d_in[6];
    const float* wo = (const float*)d_in[7];
    const float* bo = (const float*)d_in[8];
    const float* rf = (const float*)d_in[9];
    float* out = (float*)d_out;

    float2 *xs, *wqs, *wks, *wvs, *wos, *rfs, *qs, *ks, *qps, *kvts, *ats;
    float *vv, *nq, *nk, *kp, *kvp, *ksp, *ksum;
    cudaGetSymbolAddress((void**)&xs,  g_xs);
    cudaGetSymbolAddress((void**)&wqs, g_wqs);
    cudaGetSymbolAddress((void**)&wks, g_wks);
    cudaGetSymbolAddress((void**)&wvs, g_wvs);
    cudaGetSymbolAddress((void**)&wos, g_wos);
    cudaGetSymbolAddress((void**)&rfs, g_rfs);
    cudaGetSymbolAddress((void**)&qs,  g_qs);
    cudaGetSymbolAddress((void**)&ks,  g_ks);
    cudaGetSymbolAddress((void**)&vv,  g_v);
    cudaGetSymbolAddress((void**)&nq,  g_nq);
    cudaGetSymbolAddress((void**)&nk,  g_nk);
    cudaGetSymbolAddress((void**)&qps, g_qps);
    cudaGetSymbolAddress((void**)&kp,  g_kp);
    cudaGetSymbolAddress((void**)&kvp, g_kvp);
    cudaGetSymbolAddress((void**)&ksp, g_ksp);
    cudaGetSymbolAddress((void**)&kvts, g_kvts);
    cudaGetSymbolAddress((void**)&ksum, g_ksum);
    cudaGetSymbolAddress((void**)&ats, g_ats);

    const int SM128 = 2 * (128 * 36 + 128 * 36) * 8 + 2048;  // 149504
    const int SM64  = 2 * (128 * 36 +  64 * 36) * 8 + 2048;  // 112640
    cudaFuncSetAttribute(tgemm<128, 0>, cudaFuncAttributeMaxDynamicSharedMemorySize, SM128);
    cudaFuncSetAttribute(tgemm<128, 1>, cudaFuncAttributeMaxDynamicSharedMemorySize, SM128);
    cudaFuncSetAttribute(tgemm<128, 2>, cudaFuncAttributeMaxDynamicSharedMemorySize, SM128);
    cudaFuncSetAttribute(tgemm<128, 3>, cudaFuncAttributeMaxDynamicSharedMemorySize, SM128);
    cudaFuncSetAttribute(tgemm<64, 4>,  cudaFuncAttributeMaxDynamicSharedMemorySize, SM64);

    // 1) splits / transposes
    split_kernel<<<2048, 256>>>((const float4*)x, xs, Mtot * Dc / 4);
    split_kernel<<<512, 256>>>((const float4*)wq, wqs, Dc * Dc / 4);
    split_kernel<<<512, 256>>>((const float4*)wk, wks, Dc * Dc / 4);
    split_kernel<<<512, 256>>>((const float4*)wv, wvs, Dc * Dc / 4);
    split_kernel<<<512, 256>>>((const float4*)wo, wos, Dc * Dc / 4);
    rft_kernel<<<(Hc * Rc * HDc + 255) / 256, 256>>>(rf, rfs);

    // 2) projections  (M=16384, N=1024, K=1024)
    dim3 gproj(Dc / 128, Mtot / 128, 1);
    TGP pj = {};
    pj.a = xs; pj.a_ob = 0; pj.a_oh = 0; pj.a_st = Dc;
    pj.b_ob = 0; pj.b_oh = 0; pj.b_st = Dc; pj.K = Dc;
    pj.o_ob = 0; pj.o_oh = 0; pj.o_st = Dc;

    TGP pq = pj; pq.b = wqs; pq.bias = bq; pq.o0s = qs;
    tgemm<128, 1><<<gproj, 256, SM128>>>(pq);
    TGP pk = pj; pk.b = wks; pk.bias = bk; pk.o0s = ks;
    tgemm<128, 1><<<gproj, 256, SM128>>>(pk);
    TGP pv = pj; pv.b = wvs; pv.bias = bv; pv.o0 = vv;
    tgemm<128, 0><<<gproj, 256, SM128>>>(pv);

    // 3) row norms
    qnorm_kernel<<<Mtot * Hc / 8, 256>>>(qs, nq);
    qnorm_kernel<<<Mtot * Hc / 8, 256>>>(ks, nk);

    // 4) feature maps (per bh: M=4096, N=256, K=64)
    dim3 gfeat(Rc / 128, Sc / 128, Bc * Hc);
    TGP pf = {};
    pf.a_ob = (long long)Sc * Dc; pf.a_oh = HDc; pf.a_st = Dc;
    pf.b = rfs; pf.b_ob = 0; pf.b_oh = (long long)Rc * HDc; pf.b_st = HDc;
    pf.K = HDc;
    pf.o_ob = (long long)16 * Sc * Rc; pf.o_oh = (long long)Sc * Rc; pf.o_st = Rc;

    TGP pfq = pf; pfq.a = qs; pfq.norm = nq; pfq.o0s = qps;
    tgemm<128, 2><<<gfeat, 256, SM128>>>(pfq);
    TGP pfk = pf; pfk.a = ks; pfk.norm = nk; pfk.o0 = kp;
    tgemm<128, 3><<<gfeat, 256, SM128>>>(pfk);

    // 5) kv aggregation: partials + reduce -> KVT split + ksum
    dim3 gkv(Rc / 128, 8, Bc * Hc);
    kv_kernel<<<gkv, 256>>>(kp, vv, kvp, ksp);
    kvreduce_kernel<<<4096, 256>>>(kvp, ksp, kvts, ksum);

    // 6) attention readout (per bh: M=4096, N=64, K=256) + normalize
    dim3 gat(1, Sc / 128, Bc * Hc);
    TGP pa = {};
    pa.a = qps; pa.a_ob = (long long)16 * Sc * Rc; pa.a_oh = (long long)Sc * Rc; pa.a_st = Rc;
    pa.b = kvts; pa.b_ob = (long long)16 * HDc * Rc; pa.b_oh = (long long)HDc * Rc; pa.b_st = Rc;
    pa.K = Rc; pa.ksum = ksum;
    pa.o0s = ats; pa.o_ob = (long long)Sc * Dc; pa.o_oh = HDc; pa.o_st = Dc;
    tgemm<64, 4><<<gat, 256, SM64>>>(pa);

    // 7) output projection
    TGP po = pj; po.a = ats; po.b = wos; po.bias = bo; po.o0 = out;
    tgemm<128, 0><<<gproj, 256, SM128>>>(po);
}

// round 5
// speedup vs baseline: 1.3629x; 1.1511x over previous
#include <cuda_runtime.h>
#include <cstdint>
#include <math.h>

#define Bc 4
#define Sc 4096
#define Dc 1024
#define Hc 16
#define Rc 256
#define HDc 64
#define Mtot (Bc * Sc)
#define BK 32

// ---------------- scratch (device globals) ----------------
__device__ float2 g_xs[(size_t)Mtot * Dc];
__device__ float2 g_wqs[(size_t)Dc * Dc];
__device__ float2 g_wks[(size_t)Dc * Dc];
__device__ float2 g_wvs[(size_t)Dc * Dc];
__device__ float2 g_wos[(size_t)Dc * Dc];
__device__ float2 g_rfs[(size_t)Hc * Rc * HDc];
__device__ float2 g_qs[(size_t)Mtot * Dc];
__device__ float2 g_ks[(size_t)Mtot * Dc];
__device__ float  g_v[(size_t)Mtot * Dc];
__device__ float  g_nq[(size_t)Bc * Hc * Sc];
__device__ float  g_nk[(size_t)Bc * Hc * Sc];
__device__ float2 g_qps[(size_t)Bc * Hc * Sc * Rc];
__device__ float  g_kp[(size_t)Bc * Hc * Sc * Rc];
__device__ float  g_kvp[(size_t)8 * Bc * Hc * HDc * Rc];
__device__ float  g_ksp[(size_t)8 * Bc * Hc * Rc];
__device__ float2 g_kvts[(size_t)Bc * Hc * HDc * Rc];
__device__ float  g_ksum[(size_t)Bc * Hc * Rc];
__device__ float2 g_ats[(size_t)Mtot * Dc];

// ---------------- helpers ----------------
__device__ __forceinline__ uint32_t smem_u32(const void* p) {
    uint32_t a;
    asm("{ .reg .u64 t; cvta.to.shared.u64 t, %1; cvt.u32.u64 %0, t; }" : "=r"(a) : "l"(p));
    return a;
}
__device__ __forceinline__ float tf32h(float a) {
    uint32_t u;
    asm("cvt.rna.tf32.f32 %0, %1;" : "=r"(u) : "f"(a));
    return __uint_as_float(u);
}
__device__ __forceinline__ void cpa16(uint32_t dst, const void* src) {
    asm volatile("cp.async.cg.shared.global [%0], [%1], 16;"
                 :: "r"(dst), "l"(__cvta_generic_to_global(src)) : "memory");
}
__device__ __forceinline__ void mma_tf32(float* c, const uint32_t* A, const uint32_t* B) {
    asm volatile(
        "mma.sync.aligned.m16n8k8.row.col.f32.tf32.tf32.f32 "
        "{%0,%1,%2,%3}, {%4,%5,%6,%7}, {%8,%9}, {%0,%1,%2,%3};"
        : "+f"(c[0]), "+f"(c[1]), "+f"(c[2]), "+f"(c[3])
        : "r"(A[0]), "r"(A[1]), "r"(A[2]), "r"(A[3]), "r"(B[0]), "r"(B[1]));
}

// ---------------- split / transpose prep ----------------
__global__ void split_kernel(const float4* __restrict__ src, float2* __restrict__ dst, int n4)
{
    for (int i = blockIdx.x * blockDim.x + threadIdx.x; i < n4; i += gridDim.x * blockDim.x) {
        float4 a = src[i];
        float2* o = dst + (size_t)i * 4;
        float h;
        h = tf32h(a.x); o[0] = make_float2(h, tf32h(a.x - h));
        h = tf32h(a.y); o[1] = make_float2(h, tf32h(a.y - h));
        h = tf32h(a.z); o[2] = make_float2(h, tf32h(a.z - h));
        h = tf32h(a.w); o[3] = make_float2(h, tf32h(a.w - h));
    }
}
// rf[h][d][r] -> rfs[h][r][d] (split)
__global__ void rft_kernel(const float* __restrict__ rf, float2* __restrict__ out)
{
    int idx = blockIdx.x * blockDim.x + threadIdx.x;
    if (idx >= Hc * Rc * HDc) return;
    int d = idx & 63, r = (idx >> 6) & 255, h = idx >> 14;
    float a = rf[((size_t)(h * HDc + d)) * Rc + r];
    float hv = tf32h(a);
    out[idx] = make_float2(hv, tf32h(a - hv));
}

// ---------------- tensor GEMM engine ----------------
// C[128 x NTILE] per CTA, C = A * B^T in fp32 via XN-pass TF32 mma.sync.
// A, B stored as split float2 {hi, lo}.  XN=3: hh+lh+hl, XN=2: hh+lh.
// EPI: 0 +bias -> f32 out | 1 +bias -> split out + fused per-head rownorm
//      2 exp(v-0.5*norm) -> split | 3 exp(v-0.5*norm) -> f32
//      4 normalize by in-loop (A . ksum) -> split
struct TGP {
    const float2 *a, *b;
    long long a_ob, a_oh, b_ob, b_oh, o_ob, o_oh;
    int a_st, b_st, o_st, K;
    const float *bias, *norm, *ksum;
    float*  o0;       // plain out (EPI 0,3)
    float2* o0s;      // split out (EPI 1,2,4)
    float*  nrm_out;  // EPI 1
};

template<int NTILE, int EPI, int XN>
__global__ void __launch_bounds__(256, 1) tgemm(TGP p)
{
    extern __shared__ float2 smf2[];
    const int tid = threadIdx.x, lane = tid & 31, wid = tid >> 5;
    const int z = blockIdx.z;
    const int m0 = blockIdx.y << 7, n0 = blockIdx.x * NTILE;

    constexpr int MT = (NTILE == 128) ? 4 : 2;
    const int wm0 = (NTILE == 128) ? ((wid & 1) << 6) : ((wid & 3) << 5);
    const int wn0 = (NTILE == 128) ? ((wid >> 1) << 5) : ((wid >> 2) << 5);

    constexpr int ASF = 128 * 36;
    constexpr int BSF = NTILE * 36;
    float2* const A0 = smf2;
    float2* const B0 = smf2 + ASF;
    float2* const A1 = smf2 + ASF + BSF;
    float2* const B1 = smf2 + 2 * ASF + BSF;
    float* const ksums = (float*)(smf2 + 2 * (ASF + BSF));  // 256 floats (also EPI1 nsum)
    float* const snorm = ksums + 256;                        // 256 floats (EPI4)

    const size_t aoff = (size_t)p.a_ob * (z >> 4) + (size_t)p.a_oh * (z & 15);
    const size_t boff = (size_t)p.b_ob * (z >> 4) + (size_t)p.b_oh * (z & 15);
    const size_t ooff = (size_t)p.o_ob * (z >> 4) + (size_t)p.o_oh * (z & 15);

    if (EPI == 4) ksums[tid] = p.ksum[(size_t)z * Rc + tid];

    const int steps = p.K / BK;

    auto issue = [&](int step, int buf) {
        const size_t k0 = (size_t)step * BK;
        float2* Ad = buf ? A1 : A0;
        float2* Bd = buf ? B1 : B0;
        const float2* Ag = p.a + aoff + k0;
        const float2* Bg = p.b + boff + k0;
        for (int j = tid; j < 128 * 16; j += 256) {
            int row = j >> 4, seg = j & 15;
            cpa16(smem_u32(Ad + row * 36 + seg * 2),
                  Ag + (size_t)(m0 + row) * p.a_st + seg * 2);
        }
        for (int j = tid; j < NTILE * 16; j += 256) {
            int row = j >> 4, seg = j & 15;
            cpa16(smem_u32(Bd + row * 36 + seg * 2),
                  Bg + (size_t)(n0 + row) * p.b_st + seg * 2);
        }
        asm volatile("cp.async.commit_group;" ::: "memory");
    };

    issue(0, 0);
    if (steps > 1) issue(1, 1);

    float acc[MT][4][4];
    #pragma unroll
    for (int i = 0; i < MT; i++)
        #pragma unroll
        for (int j = 0; j < 4; j++)
            #pragma unroll
            for (int c = 0; c < 4; c++) acc[i][j][c] = 0.0f;
    float nacc = 0.0f;

    for (int i = 0; i < steps; i++) {
        const int buf = i & 1;
        if (i + 1 < steps) asm volatile("cp.async.wait_group 1;" ::: "memory");
        else               asm volatile("cp.async.wait_group 0;" ::: "memory");
        __syncthreads();

        const float2* As = buf ? A1 : A0;
        const float2* Bs = buf ? B1 : B0;

        if (EPI == 4) {
            const int m = tid >> 1, half = tid & 1;
            const float2* ar = As + m * 36 + half * 16;
            const float* kv = ksums + i * BK + half * 16;
            #pragma unroll
            for (int t = 0; t < 16; t++) nacc += (ar[t].x + ar[t].y) * kv[t];
        }

        #pragma unroll
        for (int kk = 0; kk < BK; kk += 8) {
            uint32_t ah[MT][4], al[MT][4];
            const int r = lane >> 2, c = lane & 3;
            #pragma unroll
            for (int im = 0; im < MT; im++) {
                const int mb = wm0 + im * 16;
                float2 e0 = As[(mb + r) * 36 + kk + c];
                float2 e1 = As[(mb + r + 8) * 36 + kk + c];
                float2 e2 = As[(mb + r) * 36 + kk + c + 4];
                float2 e3 = As[(mb + r + 8) * 36 + kk + c + 4];
                ah[im][0] = __float_as_uint(e0.x); al[im][0] = __float_as_uint(e0.y);
                ah[im][1] = __float_as_uint(e1.x); al[im][1] = __float_as_uint(e1.y);
                ah[im][2] = __float_as_uint(e2.x); al[im][2] = __float_as_uint(e2.y);
                ah[im][3] = __float_as_uint(e3.x); al[im][3] = __float_as_uint(e3.y);
            }
            #pragma unroll
            for (int in_ = 0; in_ < 4; in_++) {
                const int nb = wn0 + in_ * 8;
                float2 f0 = Bs[(nb + r) * 36 + kk + c];
                float2 f1 = Bs[(nb + r) * 36 + kk + c + 4];
                uint32_t bhv[2] = { __float_as_uint(f0.x), __float_as_uint(f1.x) };
                #pragma unroll
                for (int im = 0; im < MT; im++) {
                    mma_tf32(acc[im][in_], ah[im], bhv);
                    mma_tf32(acc[im][in_], al[im], bhv);
                }
                if (XN == 3) {
                    uint32_t blv[2] = { __float_as_uint(f0.y), __float_as_uint(f1.y) };
                    #pragma unroll
                    for (int im = 0; im < MT; im++)
                        mma_tf32(acc[im][in_], ah[im], blv);
                }
            }
        }
        __syncthreads();
        if (i + 2 < steps) issue(i + 2, buf);
    }

    if (EPI == 4) {
        snorm[tid] = nacc;
        __syncthreads();
    }
    if (EPI == 1) {
        ksums[tid] = 0.0f;   // reuse as per-(row, local-head) sumsq accumulator
        __syncthreads();
    }

    // ---------------- epilogue ----------------
    const int lh = wn0 >> 6;   // local head index within CTA tile (EPI 1)
    #pragma unroll
    for (int im = 0; im < MT; im++) {
        const int la = wm0 + im * 16 + (lane >> 2);
        const int lb = la + 8;
        const int rA = m0 + la, rB = m0 + lb;
        float hnA = 0.0f, hnB = 0.0f, invA = 1.0f, invB = 1.0f;
        if (EPI == 2 || EPI == 3) {
            hnA = 0.5f * p.norm[(size_t)z * Sc + rA];
            hnB = 0.5f * p.norm[(size_t)z * Sc + rB];
        }
        if (EPI == 4) {
            invA = 1.0f / (snorm[2 * la] + snorm[2 * la + 1] + 1e-6f);
            invB = 1.0f / (snorm[2 * lb] + snorm[2 * lb + 1] + 1e-6f);
        }
        float sA = 0.0f, sB = 0.0f;
        #pragma unroll
        for (int in_ = 0; in_ < 4; in_++) {
            const int n = n0 + wn0 + in_ * 8 + ((lane & 3) << 1);
            float v0 = acc[im][in_][0], v1 = acc[im][in_][1];
            float v2 = acc[im][in_][2], v3 = acc[im][in_][3];
            if (EPI == 0 || EPI == 1) {
                float b0 = __ldg(p.bias + n), b1 = __ldg(p.bias + n + 1);
                v0 += b0; v1 += b1; v2 += b0; v3 += b1;
            } else if (EPI == 2 || EPI == 3) {
                v0 = __expf(v0 - hnA); v1 = __expf(v1 - hnA);
                v2 = __expf(v2 - hnB); v3 = __expf(v3 - hnB);
            } else if (EPI == 4) {
                v0 *= invA; v1 *= invA; v2 *= invB; v3 *= invB;
            }
            if (EPI == 1) {
                sA += v0 * v0 + v1 * v1;
                sB += v2 * v2 + v3 * v3;
            }
            if (EPI == 0 || EPI == 3) {
                *(float2*)(p.o0 + ooff + (size_t)rA * p.o_st + n) = make_float2(v0, v1);
                *(float2*)(p.o0 + ooff + (size_t)rB * p.o_st + n) = make_float2(v2, v3);
            } else {
                float2* oA = p.o0s + ooff + (size_t)rA * p.o_st + n;
                float2* oB = p.o0s + ooff + (size_t)rB * p.o_st + n;
                float h0 = tf32h(v0), h1 = tf32h(v1), h2 = tf32h(v2), h3 = tf32h(v3);
                oA[0] = make_float2(h0, tf32h(v0 - h0));
                oA[1] = make_float2(h1, tf32h(v1 - h1));
                oB[0] = make_float2(h2, tf32h(v2 - h2));
                oB[1] = make_float2(h3, tf32h(v3 - h3));
            }
        }
        if (EPI == 1) {
            atomicAdd(&ksums[la * 2 + lh], sA);
            atomicAdd(&ksums[lb * 2 + lh], sB);
        }
    }

    if (EPI == 1) {
        __syncthreads();
        // 256 threads cover 128 rows x 2 local heads
        int row = tid >> 1, hloc = tid & 1;
        int rg = m0 + row, b = rg >> 12, s = rg & 4095;
        int head = (n0 >> 6) + hloc;
        p.nrm_out[(size_t)(b * 16 + head) * Sc + s] = ksums[tid];
    }
}

// ---------------- SIMT kv aggregation (split-K over 8 s-chunks) ----------------
__global__ void __launch_bounds__(256)
kv_kernel(const float* __restrict__ KP, const float* __restrict__ V,
          float* __restrict__ KVp, float* __restrict__ KSp)
{
    __shared__ float Ks[16][128];
    __shared__ float Vs[16][64];
    const int tid = threadIdx.x, tx = tid & 15, ty = tid >> 4;
    const int bh = blockIdx.z, b = bh >> 4, h = bh & 15;
    const int rbase = blockIdx.x << 7;
    const int sbeg = blockIdx.y << 9;
    const float* Kpb = KP + (size_t)bh * Sc * Rc;
    const float* Vb  = V + (size_t)b * Sc * Dc + h * HDc;

    float acc[8][4];
    #pragma unroll
    for (int i = 0; i < 8; i++)
        #pragma unroll
        for (int j = 0; j < 4; j++) acc[i][j] = 0.0f;
    float ks[8];
    #pragma unroll
    for (int i = 0; i < 8; i++) ks[i] = 0.0f;
    const int vrow = tid >> 4, vdseg = (tid & 15) << 2;

    for (int s0 = sbeg; s0 < sbeg + 512; s0 += 16) {
        #pragma unroll
        for (int L = 0; L < 2; L++) {
            int f = tid + (L << 8), si = f >> 5, rseg = (f & 31) << 2;
            *(float4*)(&Ks[si][rseg]) =
                *(const float4*)(Kpb + (size_t)(s0 + si) * Rc + rbase + rseg);
        }
        *(float4*)(&Vs[vrow][vdseg]) = *(const float4*)(Vb + (size_t)(s0 + vrow) * Dc + vdseg);
        __syncthreads();
        #pragma unroll
        for (int kk = 0; kk < 16; kk++) {
            float a[8], bv[4];
            *(float4*)(a)     = *(const float4*)(&Ks[kk][ty << 3]);
            *(float4*)(a + 4) = *(const float4*)(&Ks[kk][(ty << 3) + 4]);
            *(float4*)(bv)    = *(const float4*)(&Vs[kk][tx << 2]);
            #pragma unroll
            for (int i = 0; i < 8; i++)
                #pragma unroll
                for (int j = 0; j < 4; j++) acc[i][j] = fmaf(a[i], bv[j], acc[i][j]);
            if (tx == 0) {
                #pragma unroll
                for (int i = 0; i < 8; i++) ks[i] += a[i];
            }
        }
        __syncthreads();
    }
    const size_t pb = (size_t)blockIdx.y * 64 + bh;
    float* kvo = KVp + pb * HDc * Rc;
    #pragma unroll
    for (int i = 0; i < 8; i++) {
        int r = rbase + (ty << 3) + i;
        #pragma unroll
        for (int j = 0; j < 4; j++)
            kvo[(size_t)((tx << 2) + j) * Rc + r] = acc[i][j];
    }
    if (tx == 0) {
        #pragma unroll
        for (int i = 0; i < 8; i++)
            KSp[pb * Rc + rbase + (ty << 3) + i] = ks[i];
    }
}

__global__ void kvreduce_kernel(const float* __restrict__ KVp, const float* __restrict__ KSp,
                                float2* __restrict__ KVT, float* __restrict__ KS)
{
    const size_t NELEM = (size_t)64 * HDc * Rc;  // 1M
    size_t idx = (size_t)blockIdx.x * blockDim.x + threadIdx.x;
    if (idx < NELEM) {
        float s = 0.0f;
        #pragma unroll
        for (int c = 0; c < 8; c++) s += KVp[(size_t)c * NELEM + idx];
        float hv = tf32h(s);
        KVT[idx] = make_float2(hv, tf32h(s - hv));
    }
    if (idx < (size_t)64 * Rc) {
        float s = 0.0f;
        #pragma unroll
        for (int c = 0; c < 8; c++) s += KSp[(size_t)c * 64 * Rc + idx];
        KS[idx] = s;
    }
}

// ---------------- launch ----------------
extern "C" void kernel_launch(void* const* d_in, const int* in_sizes, int n_in,
                              void* d_out, int out_size)
{
    (void)in_sizes; (void)n_in; (void)out_size;
    const float* x  = (const float*)d_in[0];
    const float* wq = (const float*)d_in[1];
    const float* bq = (const float*)d_in[2];
    const float* wk = (const float*)d_in[3];
    const float* bk = (const float*)d_in[4];
    const float* wv = (const float*)d_in[5];
    const float* bv = (const float*)d_in[6];
    const float* wo = (const float*)d_in[7];
    const float* bo = (const float*)d_in[8];
    const float* rf = (const float*)d_in[9];
    float* out = (float*)d_out;

    float2 *xs, *wqs, *wks, *wvs, *wos, *rfs, *qs, *ks, *qps, *kvts, *ats;
    float *vv, *nq, *nk, *kp, *kvp, *ksp, *ksum;
    cudaGetSymbolAddress((void**)&xs,  g_xs);
    cudaGetSymbolAddress((void**)&wqs, g_wqs);
    cudaGetSymbolAddress((void**)&wks, g_wks);
    cudaGetSymbolAddress((void**)&wvs, g_wvs);
    cudaGetSymbolAddress((void**)&wos, g_wos);
    cudaGetSymbolAddress((void**)&rfs, g_rfs);
    cudaGetSymbolAddress((void**)&qs,  g_qs);
    cudaGetSymbolAddress((void**)&ks,  g_ks);
    cudaGetSymbolAddress((void**)&vv,  g_v);
    cudaGetSymbolAddress((void**)&nq,  g_nq);
    cudaGetSymbolAddress((void**)&nk,  g_nk);
    cudaGetSymbolAddress((void**)&qps, g_qps);
    cudaGetSymbolAddress((void**)&kp,  g_kp);
    cudaGetSymbolAddress((void**)&kvp, g_kvp);
    cudaGetSymbolAddress((void**)&ksp, g_ksp);
    cudaGetSymbolAddress((void**)&kvts, g_kvts);
    cudaGetSymbolAddress((void**)&ksum, g_ksum);
    cudaGetSymbolAddress((void**)&ats, g_ats);

    const int SM128 = 2 * (128 * 36 + 128 * 36) * 8 + 2048;  // 149504
    const int SM64  = 2 * (128 * 36 +  64 * 36) * 8 + 2048;  // 112640
    cudaFuncSetAttribute(tgemm<128, 0, 2>, cudaFuncAttributeMaxDynamicSharedMemorySize, SM128);
    cudaFuncSetAttribute(tgemm<128, 1, 3>, cudaFuncAttributeMaxDynamicSharedMemorySize, SM128);
    cudaFuncSetAttribute(tgemm<128, 2, 3>, cudaFuncAttributeMaxDynamicSharedMemorySize, SM128);
    cudaFuncSetAttribute(tgemm<128, 3, 3>, cudaFuncAttributeMaxDynamicSharedMemorySize, SM128);
    cudaFuncSetAttribute(tgemm<64, 4, 2>,  cudaFuncAttributeMaxDynamicSharedMemorySize, SM64);

    // launches 0-4: splits (so the tgemm below is launch index 5 -> ncu profiles it)
    split_kernel<<<2048, 256>>>((const float4*)x, xs, Mtot * Dc / 4);
    split_kernel<<<512, 256>>>((const float4*)wq, wqs, Dc * Dc / 4);
    split_kernel<<<512, 256>>>((const float4*)wk, wks, Dc * Dc / 4);
    split_kernel<<<512, 256>>>((const float4*)wv, wvs, Dc * Dc / 4);
    split_kernel<<<512, 256>>>((const float4*)wo, wos, Dc * Dc / 4);

    // projections (M=16384, N=1024, K=1024)
    dim3 gproj(Dc / 128, Mtot / 128, 1);
    TGP pj = {};
    pj.a = xs; pj.a_ob = 0; pj.a_oh = 0; pj.a_st = Dc;
    pj.b_ob = 0; pj.b_oh = 0; pj.b_st = Dc; pj.K = Dc;
    pj.o_ob = 0; pj.o_oh = 0; pj.o_st = Dc;

    TGP pq = pj; pq.b = wqs; pq.bias = bq; pq.o0s = qs; pq.nrm_out = nq;
    tgemm<128, 1, 3><<<gproj, 256, SM128>>>(pq);   // launch #5 -> profiled
    TGP pk = pj; pk.b = wks; pk.bias = bk; pk.o0s = ks; pk.nrm_out = nk;
    tgemm<128, 1, 3><<<gproj, 256, SM128>>>(pk);
    TGP pv = pj; pv.b = wvs; pv.bias = bv; pv.o0 = vv;
    tgemm<128, 0, 2><<<gproj, 256, SM128>>>(pv);

    rft_kernel<<<(Hc * Rc * HDc + 255) / 256, 256>>>(rf, rfs);

    // feature maps (per bh: M=4096, N=256, K=64)
    dim3 gfeat(Rc / 128, Sc / 128, Bc * Hc);
    TGP pf = {};
    pf.a_ob = (long long)Sc * Dc; pf.a_oh = HDc; pf.a_st = Dc;
    pf.b = rfs; pf.b_ob = 0; pf.b_oh = (long long)Rc * HDc; pf.b_st = HDc;
    pf.K = HDc;
    pf.o_ob = (long long)16 * Sc * Rc; pf.o_oh = (long long)Sc * Rc; pf.o_st = Rc;

    TGP pfq = pf; pfq.a = qs; pfq.norm = nq; pfq.o0s = qps;
    tgemm<128, 2, 3><<<gfeat, 256, SM128>>>(pfq);
    TGP pfk = pf; pfk.a = ks; pfk.norm = nk; pfk.o0 = kp;
    tgemm<128, 3, 3><<<gfeat, 256, SM128>>>(pfk);

    // kv aggregation: partials + reduce -> KVT split + ksum
    dim3 gkv(Rc / 128, 8, Bc * Hc);
    kv_kernel<<<gkv, 256>>>(kp, vv, kvp, ksp);
    kvreduce_kernel<<<4096, 256>>>(kvp, ksp, kvts, ksum);

    // attention readout (per bh: M=4096, N=64, K=256) + normalize
    dim3 gat(1, Sc / 128, Bc * Hc);
    TGP pa = {};
    pa.a = qps; pa.a_ob = (long long)16 * Sc * Rc; pa.a_oh = (long long)Sc * Rc; pa.a_st = Rc;
    pa.b = kvts; pa.b_ob = (long long)16 * HDc * Rc; pa.b_oh = (long long)HDc * Rc; pa.b_st = Rc;
    pa.K = Rc; pa.ksum = ksum;
    pa.o0s = ats; pa.o_ob = (long long)Sc * Dc; pa.o_oh = HDc; pa.o_st = Dc;
    tgemm<64, 4, 2><<<gat, 256, SM64>>>(pa);

    // output projection
    TGP po = pj; po.a = ats; po.b = wos; po.bias = bo; po.o0 = out;
    tgemm<128, 0, 2><<<gproj, 256, SM128>>>(po);
}

// round 6
// speedup vs baseline: 1.4129x; 1.0367x over previous
#include <cuda_runtime.h>
#include <cstdint>
#include <math.h>

#define Bc 4
#define Sc 4096
#define Dc 1024
#define Hc 16
#define Rc 256
#define HDc 64
#define Mtot (Bc * Sc)
#define BK 16
#define ST 20   // smem row stride in float2 (16 + 4 pad)

// ---------------- scratch (device globals) ----------------
__device__ float2 g_xs[(size_t)Mtot * Dc];
__device__ float2 g_wqs[(size_t)Dc * Dc];
__device__ float2 g_wks[(size_t)Dc * Dc];
__device__ float2 g_wvs[(size_t)Dc * Dc];
__device__ float2 g_wos[(size_t)Dc * Dc];
__device__ float2 g_rfs[(size_t)Hc * Rc * HDc];
__device__ float2 g_qs[(size_t)Mtot * Dc];
__device__ float2 g_ks[(size_t)Mtot * Dc];
__device__ float  g_v[(size_t)Mtot * Dc];
__device__ float  g_nq[(size_t)Bc * Hc * Sc];
__device__ float  g_nk[(size_t)Bc * Hc * Sc];
__device__ float2 g_qps[(size_t)Bc * Hc * Sc * Rc];
__device__ float  g_kp[(size_t)Bc * Hc * Sc * Rc];
__device__ float  g_kvp[(size_t)8 * Bc * Hc * HDc * Rc];
__device__ float  g_ksp[(size_t)8 * Bc * Hc * Rc];
__device__ float2 g_kvts[(size_t)Bc * Hc * HDc * Rc];
__device__ float  g_ksum[(size_t)Bc * Hc * Rc];
__device__ float2 g_ats[(size_t)Mtot * Dc];

// ---------------- helpers ----------------
__device__ __forceinline__ uint32_t smem_u32(const void* p) {
    uint32_t a;
    asm("{ .reg .u64 t; cvta.to.shared.u64 t, %1; cvt.u32.u64 %0, t; }" : "=r"(a) : "l"(p));
    return a;
}
__device__ __forceinline__ float tf32h(float a) {
    uint32_t u;
    asm("cvt.rna.tf32.f32 %0, %1;" : "=r"(u) : "f"(a));
    return __uint_as_float(u);
}
__device__ __forceinline__ void cpa16(uint32_t dst, const void* src) {
    asm volatile("cp.async.cg.shared.global [%0], [%1], 16;"
                 :: "r"(dst), "l"(__cvta_generic_to_global(src)) : "memory");
}
__device__ __forceinline__ void mma_tf32(float* c, const uint32_t* A, const uint32_t* B) {
    asm volatile(
        "mma.sync.aligned.m16n8k8.row.col.f32.tf32.tf32.f32 "
        "{%0,%1,%2,%3}, {%4,%5,%6,%7}, {%8,%9}, {%0,%1,%2,%3};"
        : "+f"(c[0]), "+f"(c[1]), "+f"(c[2]), "+f"(c[3])
        : "r"(A[0]), "r"(A[1]), "r"(A[2]), "r"(A[3]), "r"(B[0]), "r"(B[1]));
}

// ---------------- split / transpose prep ----------------
__global__ void split_kernel(const float4* __restrict__ src, float2* __restrict__ dst, int n4)
{
    for (int i = blockIdx.x * blockDim.x + threadIdx.x; i < n4; i += gridDim.x * blockDim.x) {
        float4 a = src[i];
        float2* o = dst + (size_t)i * 4;
        float h;
        h = tf32h(a.x); o[0] = make_float2(h, tf32h(a.x - h));
        h = tf32h(a.y); o[1] = make_float2(h, tf32h(a.y - h));
        h = tf32h(a.z); o[2] = make_float2(h, tf32h(a.z - h));
        h = tf32h(a.w); o[3] = make_float2(h, tf32h(a.w - h));
    }
}
// rf[h][d][r] -> rfs[h][r][d] (split)
__global__ void rft_kernel(const float* __restrict__ rf, float2* __restrict__ out)
{
    int idx = blockIdx.x * blockDim.x + threadIdx.x;
    if (idx >= Hc * Rc * HDc) return;
    int d = idx & 63, r = (idx >> 6) & 255, h = idx >> 14;
    float a = rf[((size_t)(h * HDc + d)) * Rc + r];
    float hv = tf32h(a);
    out[idx] = make_float2(hv, tf32h(a - hv));
}

// ---------------- tensor GEMM engine ----------------
// C[128 x NTILE] per CTA, C = A * B^T in fp32 via XN-pass TF32 mma.sync.
// A, B stored as split float2 {hi, lo}.  XN=3: hh+lh+hl, XN=2: hh+lh.
// EPI: 0 +bias -> f32 out | 1 +bias -> split out + fused per-head rownorm
//      2 exp(v-0.5*norm) -> split | 3 exp(v-0.5*norm) -> f32
//      4 normalize by in-loop (A . ksum) -> split
struct TGP {
    const float2 *a, *b;
    long long a_ob, a_oh, b_ob, b_oh, o_ob, o_oh;
    int a_st, b_st, o_st, K;
    const float *bias, *norm, *ksum;
    float*  o0;       // plain out (EPI 0,3)
    float2* o0s;      // split out (EPI 1,2,4)
    float*  nrm_out;  // EPI 1
};

template<int NTILE, int EPI, int XN>
__global__ void __launch_bounds__(256, 2) tgemm(TGP p)
{
    extern __shared__ float2 smf2[];
    const int tid = threadIdx.x, lane = tid & 31, wid = tid >> 5;
    const int z = blockIdx.z;
    const int m0 = blockIdx.y << 7, n0 = blockIdx.x * NTILE;

    constexpr int MT = (NTILE == 128) ? 4 : 2;
    const int wm0 = (NTILE == 128) ? ((wid & 1) << 6) : ((wid & 3) << 5);
    const int wn0 = (NTILE == 128) ? ((wid >> 1) << 5) : ((wid >> 2) << 5);

    constexpr int ASF = 128 * ST;
    constexpr int BSF = NTILE * ST;
    float2* const A0 = smf2;
    float2* const B0 = smf2 + ASF;
    float2* const A1 = smf2 + ASF + BSF;
    float2* const B1 = smf2 + 2 * ASF + BSF;
    float* const ksums = (float*)(smf2 + 2 * (ASF + BSF));  // 256 floats (also EPI1 nsum)
    float* const snorm = ksums + 256;                        // 256 floats (EPI4)

    const size_t aoff = (size_t)p.a_ob * (z >> 4) + (size_t)p.a_oh * (z & 15);
    const size_t boff = (size_t)p.b_ob * (z >> 4) + (size_t)p.b_oh * (z & 15);
    const size_t ooff = (size_t)p.o_ob * (z >> 4) + (size_t)p.o_oh * (z & 15);

    if (EPI == 4) ksums[tid] = p.ksum[(size_t)z * Rc + tid];

    const int steps = p.K / BK;

    auto issue = [&](int step, int buf) {
        const size_t k0 = (size_t)step * BK;
        float2* Ad = buf ? A1 : A0;
        float2* Bd = buf ? B1 : B0;
        const float2* Ag = p.a + aoff + k0;
        const float2* Bg = p.b + boff + k0;
        for (int j = tid; j < 128 * 8; j += 256) {
            int row = j >> 3, seg = j & 7;
            cpa16(smem_u32(Ad + row * ST + seg * 2),
                  Ag + (size_t)(m0 + row) * p.a_st + seg * 2);
        }
        for (int j = tid; j < NTILE * 8; j += 256) {
            int row = j >> 3, seg = j & 7;
            cpa16(smem_u32(Bd + row * ST + seg * 2),
                  Bg + (size_t)(n0 + row) * p.b_st + seg * 2);
        }
        asm volatile("cp.async.commit_group;" ::: "memory");
    };

    issue(0, 0);
    if (steps > 1) issue(1, 1);

    float acc[MT][4][4];
    #pragma unroll
    for (int i = 0; i < MT; i++)
        #pragma unroll
        for (int j = 0; j < 4; j++)
            #pragma unroll
            for (int c = 0; c < 4; c++) acc[i][j][c] = 0.0f;
    float nacc = 0.0f;

    for (int i = 0; i < steps; i++) {
        const int buf = i & 1;
        if (i + 1 < steps) asm volatile("cp.async.wait_group 1;" ::: "memory");
        else               asm volatile("cp.async.wait_group 0;" ::: "memory");
        __syncthreads();

        const float2* As = buf ? A1 : A0;
        const float2* Bs = buf ? B1 : B0;

        if (EPI == 4) {
            const int m = tid >> 1, half = tid & 1;
            const float2* ar = As + m * ST + half * 8;
            const float* kv = ksums + i * BK + half * 8;
            #pragma unroll
            for (int t = 0; t < 8; t++) nacc += (ar[t].x + ar[t].y) * kv[t];
        }

        #pragma unroll
        for (int kk = 0; kk < BK; kk += 8) {
            uint32_t ah[MT][4], al[MT][4];
            const int r = lane >> 2, c = lane & 3;
            #pragma unroll
            for (int im = 0; im < MT; im++) {
                const int mb = wm0 + im * 16;
                float2 e0 = As[(mb + r) * ST + kk + c];
                float2 e1 = As[(mb + r + 8) * ST + kk + c];
                float2 e2 = As[(mb + r) * ST + kk + c + 4];
                float2 e3 = As[(mb + r + 8) * ST + kk + c + 4];
                ah[im][0] = __float_as_uint(e0.x); al[im][0] = __float_as_uint(e0.y);
                ah[im][1] = __float_as_uint(e1.x); al[im][1] = __float_as_uint(e1.y);
                ah[im][2] = __float_as_uint(e2.x); al[im][2] = __float_as_uint(e2.y);
                ah[im][3] = __float_as_uint(e3.x); al[im][3] = __float_as_uint(e3.y);
            }
            #pragma unroll
            for (int in_ = 0; in_ < 4; in_++) {
                const int nb = wn0 + in_ * 8;
                float2 f0 = Bs[(nb + r) * ST + kk + c];
                float2 f1 = Bs[(nb + r) * ST + kk + c + 4];
                uint32_t bhv[2] = { __float_as_uint(f0.x), __float_as_uint(f1.x) };
                // pass-major ordering: dependent writes to the same acc are
                // separated by MT independent HMMAs
                #pragma unroll
                for (int im = 0; im < MT; im++) mma_tf32(acc[im][in_], ah[im], bhv);
                #pragma unroll
                for (int im = 0; im < MT; im++) mma_tf32(acc[im][in_], al[im], bhv);
                if (XN == 3) {
                    uint32_t blv[2] = { __float_as_uint(f0.y), __float_as_uint(f1.y) };
                    #pragma unroll
                    for (int im = 0; im < MT; im++) mma_tf32(acc[im][in_], ah[im], blv);
                }
            }
        }
        __syncthreads();
        if (i + 2 < steps) issue(i + 2, buf);
    }

    if (EPI == 4) {
        snorm[tid] = nacc;
        __syncthreads();
    }
    if (EPI == 1) {
        ksums[tid] = 0.0f;   // reuse as per-(row, local-head) sumsq accumulator
        __syncthreads();
    }

    // ---------------- epilogue ----------------
    const int lh = wn0 >> 6;   // local head index within CTA tile (EPI 1)
    #pragma unroll
    for (int im = 0; im < MT; im++) {
        const int la = wm0 + im * 16 + (lane >> 2);
        const int lb = la + 8;
        const int rA = m0 + la, rB = m0 + lb;
        float hnA = 0.0f, hnB = 0.0f, invA = 1.0f, invB = 1.0f;
        if (EPI == 2 || EPI == 3) {
            hnA = 0.5f * p.norm[(size_t)z * Sc + rA];
            hnB = 0.5f * p.norm[(size_t)z * Sc + rB];
        }
        if (EPI == 4) {
            invA = 1.0f / (snorm[2 * la] + snorm[2 * la + 1] + 1e-6f);
            invB = 1.0f / (snorm[2 * lb] + snorm[2 * lb + 1] + 1e-6f);
        }
        float sA = 0.0f, sB = 0.0f;
        #pragma unroll
        for (int in_ = 0; in_ < 4; in_++) {
            const int n = n0 + wn0 + in_ * 8 + ((lane & 3) << 1);
            float v0 = acc[im][in_][0], v1 = acc[im][in_][1];
            float v2 = acc[im][in_][2], v3 = acc[im][in_][3];
            if (EPI == 0 || EPI == 1) {
                float b0 = __ldg(p.bias + n), b1 = __ldg(p.bias + n + 1);
                v0 += b0; v1 += b1; v2 += b0; v3 += b1;
            } else if (EPI == 2 || EPI == 3) {
                v0 = __expf(v0 - hnA); v1 = __expf(v1 - hnA);
                v2 = __expf(v2 - hnB); v3 = __expf(v3 - hnB);
            } else if (EPI == 4) {
                v0 *= invA; v1 *= invA; v2 *= invB; v3 *= invB;
            }
            if (EPI == 1) {
                sA += v0 * v0 + v1 * v1;
                sB += v2 * v2 + v3 * v3;
            }
            if (EPI == 0 || EPI == 3) {
                *(float2*)(p.o0 + ooff + (size_t)rA * p.o_st + n) = make_float2(v0, v1);
                *(float2*)(p.o0 + ooff + (size_t)rB * p.o_st + n) = make_float2(v2, v3);
            } else {
                float2* oA = p.o0s + ooff + (size_t)rA * p.o_st + n;
                float2* oB = p.o0s + ooff + (size_t)rB * p.o_st + n;
                float h0 = tf32h(v0), h1 = tf32h(v1), h2 = tf32h(v2), h3 = tf32h(v3);
                oA[0] = make_float2(h0, tf32h(v0 - h0));
                oA[1] = make_float2(h1, tf32h(v1 - h1));
                oB[0] = make_float2(h2, tf32h(v2 - h2));
                oB[1] = make_float2(h3, tf32h(v3 - h3));
            }
        }
        if (EPI == 1) {
            atomicAdd(&ksums[la * 2 + lh], sA);
            atomicAdd(&ksums[lb * 2 + lh], sB);
        }
    }

    if (EPI == 1) {
        __syncthreads();
        // 256 threads cover 128 rows x 2 local heads
        int row = tid >> 1, hloc = tid & 1;
        int rg = m0 + row, b = rg >> 12, s = rg & 4095;
        int head = (n0 >> 6) + hloc;
        p.nrm_out[(size_t)(b * 16 + head) * Sc + s] = ksums[tid];
    }
}

// ---------------- SIMT kv aggregation (split-K over 8 s-chunks) ----------------
__global__ void __launch_bounds__(256)
kv_kernel(const float* __restrict__ KP, const float* __restrict__ V,
          float* __restrict__ KVp, float* __restrict__ KSp)
{
    __shared__ float Ks[16][128];
    __shared__ float Vs[16][64];
    const int tid = threadIdx.x, tx = tid & 15, ty = tid >> 4;
    const int bh = blockIdx.z, b = bh >> 4, h = bh & 15;
    const int rbase = blockIdx.x << 7;
    const int sbeg = blockIdx.y << 9;
    const float* Kpb = KP + (size_t)bh * Sc * Rc;
    const float* Vb  = V + (size_t)b * Sc * Dc + h * HDc;

    float acc[8][4];
    #pragma unroll
    for (int i = 0; i < 8; i++)
        #pragma unroll
        for (int j = 0; j < 4; j++) acc[i][j] = 0.0f;
    float ks[8];
    #pragma unroll
    for (int i = 0; i < 8; i++) ks[i] = 0.0f;
    const int vrow = tid >> 4, vdseg = (tid & 15) << 2;

    for (int s0 = sbeg; s0 < sbeg + 512; s0 += 16) {
        #pragma unroll
        for (int L = 0; L < 2; L++) {
            int f = tid + (L << 8), si = f >> 5, rseg = (f & 31) << 2;
            *(float4*)(&Ks[si][rseg]) =
                *(const float4*)(Kpb + (size_t)(s0 + si) * Rc + rbase + rseg);
        }
        *(float4*)(&Vs[vrow][vdseg]) = *(const float4*)(Vb + (size_t)(s0 + vrow) * Dc + vdseg);
        __syncthreads();
        #pragma unroll
        for (int kk = 0; kk < 16; kk++) {
            float a[8], bv[4];
            *(float4*)(a)     = *(const float4*)(&Ks[kk][ty << 3]);
            *(float4*)(a + 4) = *(const float4*)(&Ks[kk][(ty << 3) + 4]);
            *(float4*)(bv)    = *(const float4*)(&Vs[kk][tx << 2]);
            #pragma unroll
            for (int i = 0; i < 8; i++)
                #pragma unroll
                for (int j = 0; j < 4; j++) acc[i][j] = fmaf(a[i], bv[j], acc[i][j]);
            if (tx == 0) {
                #pragma unroll
                for (int i = 0; i < 8; i++) ks[i] += a[i];
            }
        }
        __syncthreads();
    }
    const size_t pb = (size_t)blockIdx.y * 64 + bh;
    float* kvo = KVp + pb * HDc * Rc;
    #pragma unroll
    for (int i = 0; i < 8; i++) {
        int r = rbase + (ty << 3) + i;
        #pragma unroll
        for (int j = 0; j < 4; j++)
            kvo[(size_t)((tx << 2) + j) * Rc + r] = acc[i][j];
    }
    if (tx == 0) {
        #pragma unroll
        for (int i = 0; i < 8; i++)
            KSp[pb * Rc + rbase + (ty << 3) + i] = ks[i];
    }
}

__global__ void kvreduce_kernel(const float* __restrict__ KVp, const float* __restrict__ KSp,
                                float2* __restrict__ KVT, float* __restrict__ KS)
{
    const size_t NELEM = (size_t)64 * HDc * Rc;  // 1M
    size_t idx = (size_t)blockIdx.x * blockDim.x + threadIdx.x;
    if (idx < NELEM) {
        float s = 0.0f;
        #pragma unroll
        for (int c = 0; c < 8; c++) s += KVp[(size_t)c * NELEM + idx];
        float hv = tf32h(s);
        KVT[idx] = make_float2(hv, tf32h(s - hv));
    }
    if (idx < (size_t)64 * Rc) {
        float s = 0.0f;
        #pragma unroll
        for (int c = 0; c < 8; c++) s += KSp[(size_t)c * 64 * Rc + idx];
        KS[idx] = s;
    }
}

// ---------------- launch ----------------
extern "C" void kernel_launch(void* const* d_in, const int* in_sizes, int n_in,
                              void* d_out, int out_size)
{
    (void)in_sizes; (void)n_in; (void)out_size;
    const float* x  = (const float*)d_in[0];
    const float* wq = (const float*)d_in[1];
    const float* bq = (const float*)d_in[2];
    const float* wk = (const float*)d_in[3];
    const float* bk = (const float*)d_in[4];
    const float* wv = (const float*)d_in[5];
    const float* bv = (const float*)d_in[6];
    const float* wo = (const float*)d_in[7];
    const float* bo = (const float*)d_in[8];
    const float* rf = (const float*)d_in[9];
    float* out = (float*)d_out;

    float2 *xs, *wqs, *wks, *wvs, *wos, *rfs, *qs, *ks, *qps, *kvts, *ats;
    float *vv, *nq, *nk, *kp, *kvp, *ksp, *ksum;
    cudaGetSymbolAddress((void**)&xs,  g_xs);
    cudaGetSymbolAddress((void**)&wqs, g_wqs);
    cudaGetSymbolAddress((void**)&wks, g_wks);
    cudaGetSymbolAddress((void**)&wvs, g_wvs);
    cudaGetSymbolAddress((void**)&wos, g_wos);
    cudaGetSymbolAddress((void**)&rfs, g_rfs);
    cudaGetSymbolAddress((void**)&qs,  g_qs);
    cudaGetSymbolAddress((void**)&ks,  g_ks);
    cudaGetSymbolAddress((void**)&vv,  g_v);
    cudaGetSymbolAddress((void**)&nq,  g_nq);
    cudaGetSymbolAddress((void**)&nk,  g_nk);
    cudaGetSymbolAddress((void**)&qps, g_qps);
    cudaGetSymbolAddress((void**)&kp,  g_kp);
    cudaGetSymbolAddress((void**)&kvp, g_kvp);
    cudaGetSymbolAddress((void**)&ksp, g_ksp);
    cudaGetSymbolAddress((void**)&kvts, g_kvts);
    cudaGetSymbolAddress((void**)&ksum, g_ksum);
    cudaGetSymbolAddress((void**)&ats, g_ats);

    const int SM128 = 2 * (128 * ST + 128 * ST) * 8 + 2048;  // 83968
    const int SM64  = 2 * (128 * ST +  64 * ST) * 8 + 2048;  // 63488
    cudaFuncSetAttribute(tgemm<128, 0, 2>, cudaFuncAttributeMaxDynamicSharedMemorySize, SM128);
    cudaFuncSetAttribute(tgemm<128, 1, 3>, cudaFuncAttributeMaxDynamicSharedMemorySize, SM128);
    cudaFuncSetAttribute(tgemm<128, 2, 3>, cudaFuncAttributeMaxDynamicSharedMemorySize, SM128);
    cudaFuncSetAttribute(tgemm<128, 3, 3>, cudaFuncAttributeMaxDynamicSharedMemorySize, SM128);
    cudaFuncSetAttribute(tgemm<64, 4, 2>,  cudaFuncAttributeMaxDynamicSharedMemorySize, SM64);

    // splits
    split_kernel<<<2048, 256>>>((const float4*)x, xs, Mtot * Dc / 4);
    split_kernel<<<512, 256>>>((const float4*)wq, wqs, Dc * Dc / 4);
    split_kernel<<<512, 256>>>((const float4*)wk, wks, Dc * Dc / 4);
    split_kernel<<<512, 256>>>((const float4*)wv, wvs, Dc * Dc / 4);
    split_kernel<<<512, 256>>>((const float4*)wo, wos, Dc * Dc / 4);

    // projections (M=16384, N=1024, K=1024)
    dim3 gproj(Dc / 128, Mtot / 128, 1);
    TGP pj = {};
    pj.a = xs; pj.a_ob = 0; pj.a_oh = 0; pj.a_st = Dc;
    pj.b_ob = 0; pj.b_oh = 0; pj.b_st = Dc; pj.K = Dc;
    pj.o_ob = 0; pj.o_oh = 0; pj.o_st = Dc;

    TGP pq = pj; pq.b = wqs; pq.bias = bq; pq.o0s = qs; pq.nrm_out = nq;
    tgemm<128, 1, 3><<<gproj, 256, SM128>>>(pq);
    TGP pk = pj; pk.b = wks; pk.bias = bk; pk.o0s = ks; pk.nrm_out = nk;
    tgemm<128, 1, 3><<<gproj, 256, SM128>>>(pk);
    TGP pv = pj; pv.b = wvs; pv.bias = bv; pv.o0 = vv;
    tgemm<128, 0, 2><<<gproj, 256, SM128>>>(pv);

    rft_kernel<<<(Hc * Rc * HDc + 255) / 256, 256>>>(rf, rfs);

    // feature maps (per bh: M=4096, N=256, K=64)
    dim3 gfeat(Rc / 128, Sc / 128, Bc * Hc);
    TGP pf = {};
    pf.a_ob = (long long)Sc * Dc; pf.a_oh = HDc; pf.a_st = Dc;
    pf.b = rfs; pf.b_ob = 0; pf.b_oh = (long long)Rc * HDc; pf.b_st = HDc;
    pf.K = HDc;
    pf.o_ob = (long long)16 * Sc * Rc; pf.o_oh = (long long)Sc * Rc; pf.o_st = Rc;

    TGP pfq = pf; pfq.a = qs; pfq.norm = nq; pfq.o0s = qps;
    tgemm<128, 2, 3><<<gfeat, 256, SM128>>>(pfq);
    TGP pfk = pf; pfk.a = ks; pfk.norm = nk; pfk.o0 = kp;
    tgemm<128, 3, 3><<<gfeat, 256, SM128>>>(pfk);

    // kv aggregation: partials + reduce -> KVT split + ksum
    dim3 gkv(Rc / 128, 8, Bc * Hc);
    kv_kernel<<<gkv, 256>>>(kp, vv, kvp, ksp);
    kvreduce_kernel<<<4096, 256>>>(kvp, ksp, kvts, ksum);

    // attention readout (per bh: M=4096, N=64, K=256) + normalize
    dim3 gat(1, Sc / 128, Bc * Hc);
    TGP pa = {};
    pa.a = qps; pa.a_ob = (long long)16 * Sc * Rc; pa.a_oh = (long long)Sc * Rc; pa.a_st = Rc;
    pa.b = kvts; pa.b_ob = (long long)16 * HDc * Rc; pa.b_oh = (long long)HDc * Rc; pa.b_st = Rc;
    pa.K = Rc; pa.ksum = ksum;
    pa.o0s = ats; pa.o_ob = (long long)Sc * Dc; pa.o_oh = HDc; pa.o_st = Dc;
    tgemm<64, 4, 2><<<gat, 256, SM64>>>(pa);

    // output projection
    TGP po = pj; po.a = ats; po.b = wos; po.bias = bo; po.o0 = out;
    tgemm<128, 0, 2><<<gproj, 256, SM128>>>(po);
}

// round 7
// speedup vs baseline: 2.2677x; 1.6049x over previous
#include <cuda_runtime.h>
#include <cuda_bf16.h>
#include <cstdint>
#include <math.h>

#define Bc 4
#define Sc 4096
#define Dc 1024
#define Hc 16
#define Rc 256
#define HDc 64
#define Mtot (Bc * Sc)

typedef unsigned short u16;
typedef uint32_t u32;

// ---------------- scratch (device globals) ----------------
__device__ u16 g_xh[(size_t)Mtot * Dc],  g_xl[(size_t)Mtot * Dc];
__device__ u16 g_wqh[Dc * Dc], g_wql[Dc * Dc];
__device__ u16 g_wkh[Dc * Dc], g_wkl[Dc * Dc];
__device__ u16 g_wvh[Dc * Dc], g_wvl[Dc * Dc];
__device__ u16 g_woh[Dc * Dc], g_wol[Dc * Dc];
__device__ u16 g_rfh[(size_t)Hc * Rc * HDc], g_rfl[(size_t)Hc * Rc * HDc];
__device__ u16 g_qh[(size_t)Mtot * Dc],  g_ql[(size_t)Mtot * Dc];
__device__ u16 g_kh[(size_t)Mtot * Dc],  g_kl[(size_t)Mtot * Dc];
__device__ float g_v[(size_t)Mtot * Dc];
__device__ float g_nq[(size_t)Bc * Hc * Sc], g_nk[(size_t)Bc * Hc * Sc];
__device__ u16 g_qph[(size_t)Bc * Hc * Sc * Rc], g_qpl[(size_t)Bc * Hc * Sc * Rc];
__device__ float g_kp[(size_t)Bc * Hc * Sc * Rc];
__device__ float g_kvp[(size_t)8 * Bc * Hc * HDc * Rc];
__device__ float g_ksp[(size_t)8 * Bc * Hc * Rc];
__device__ u16 g_kvth[(size_t)Bc * Hc * HDc * Rc], g_kvtl[(size_t)Bc * Hc * HDc * Rc];
__device__ float g_ksum[(size_t)Bc * Hc * Rc];
__device__ u16 g_ath[(size_t)Mtot * Dc], g_atl[(size_t)Mtot * Dc];

// ---------------- helpers ----------------
__device__ __forceinline__ u32 smem_u32(const void* p) {
    u32 a;
    asm("{ .reg .u64 t; cvta.to.shared.u64 t, %1; cvt.u32.u64 %0, t; }" : "=r"(a) : "l"(p));
    return a;
}
__device__ __forceinline__ void bsplit(float a, u16& h, u16& l) {
    __nv_bfloat16 hb = __float2bfloat16_rn(a);
    float lf = a - __bfloat162float(hb);
    __nv_bfloat16 lb = __float2bfloat16_rn(lf);
    h = __bfloat16_as_ushort(hb);
    l = __bfloat16_as_ushort(lb);
}
__device__ __forceinline__ void cpa16(u32 dst, const void* src) {
    asm volatile("cp.async.cg.shared.global [%0], [%1], 16;"
                 :: "r"(dst), "l"(__cvta_generic_to_global(src)) : "memory");
}
__device__ __forceinline__ void mma_bf16(float* c, const u32* A, const u32* B) {
    asm volatile(
        "mma.sync.aligned.m16n8k16.row.col.f32.bf16.bf16.f32 "
        "{%0,%1,%2,%3}, {%4,%5,%6,%7}, {%8,%9}, {%0,%1,%2,%3};"
        : "+f"(c[0]), "+f"(c[1]), "+f"(c[2]), "+f"(c[3])
        : "r"(A[0]), "r"(A[1]), "r"(A[2]), "r"(A[3]), "r"(B[0]), "r"(B[1]));
}

// ---------------- split / transpose prep ----------------
__global__ void split_kernel(const float4* __restrict__ src, u16* __restrict__ hi,
                             u16* __restrict__ lo, int n4)
{
    for (int i = blockIdx.x * blockDim.x + threadIdx.x; i < n4; i += gridDim.x * blockDim.x) {
        float4 a = src[i];
        ushort4 hv, lv;
        bsplit(a.x, hv.x, lv.x); bsplit(a.y, hv.y, lv.y);
        bsplit(a.z, hv.z, lv.z); bsplit(a.w, hv.w, lv.w);
        *(ushort4*)(hi + (size_t)i * 4) = hv;
        *(ushort4*)(lo + (size_t)i * 4) = lv;
    }
}
// rf[h][d][r] -> planes [h][r][d]
__global__ void rft_kernel(const float* __restrict__ rf, u16* __restrict__ oh,
                           u16* __restrict__ ol)
{
    int idx = blockIdx.x * blockDim.x + threadIdx.x;
    if (idx >= Hc * Rc * HDc) return;
    int d = idx & 63, r = (idx >> 6) & 255, h = idx >> 14;
    float a = rf[((size_t)(h * HDc + d)) * Rc + r];
    u16 hv, lv; bsplit(a, hv, lv);
    oh[idx] = hv; ol[idx] = lv;
}

// ---------------- bf16x3 tensor GEMM engine ----------------
// C[128 x NTILE] per CTA; C = A * B^T (fp32 accum), 3-pass bf16 (hh+lh+hl).
// Operands as separate hi/lo bf16 planes.
// EPI: 0 +bias -> f32 | 1 +bias -> split + fused per-head rownorm
//      2 exp(v-0.5*norm) -> split | 3 exp(v-0.5*norm) -> f32
//      4 normalize by in-loop (A . ksum) -> split
struct TGP {
    const u16 *ah, *al, *bh, *bl;
    long long a_ob, a_oh, b_ob, b_oh, o_ob, o_oh;
    int a_st, b_st, o_st, K;
    const float *bias, *norm, *ksum;
    float* o0;
    u16 *o_hi, *o_lo;
    float* nrm_out;
};

template<int NTILE, int EPI>
__global__ void __launch_bounds__(256, 2) tgemm(TGP p)
{
    extern __shared__ char smc[];
    const int tid = threadIdx.x, lane = tid & 31, wid = tid >> 5;
    const int z = blockIdx.z;
    const int m0 = blockIdx.y << 7, n0 = blockIdx.x * NTILE;

    constexpr int MT = (NTILE == 128) ? 4 : 2;
    const int wm0 = (NTILE == 128) ? ((wid & 1) << 6) : ((wid & 3) << 5);
    const int wn0 = (NTILE == 128) ? ((wid >> 1) << 5) : ((wid >> 2) << 5);

    constexpr int ASZ = 128 * 48;       // bytes per A plane (row stride 48B = 24 u16)
    constexpr int BSZ = NTILE * 48;
    constexpr int BLK = 2 * ASZ + 2 * BSZ;
    char* const base = smc;
    float* const ksums = (float*)(base + 2 * BLK);   // 256 f
    float* const snorm = ksums + 256;                 // 256 f

    const size_t aoff = (size_t)p.a_ob * (z >> 4) + (size_t)p.a_oh * (z & 15);
    const size_t boff = (size_t)p.b_ob * (z >> 4) + (size_t)p.b_oh * (z & 15);
    const size_t ooff = (size_t)p.o_ob * (z >> 4) + (size_t)p.o_oh * (z & 15);

    if (EPI == 4) ksums[tid] = p.ksum[(size_t)z * Rc + tid];

    const int steps = p.K / 16;

    auto issue = [&](int step, int buf) {
        const int k0 = step * 16;
        u16* ah_s = (u16*)(base + buf * BLK);
        u16* al_s = (u16*)(base + buf * BLK + ASZ);
        u16* bh_s = (u16*)(base + buf * BLK + 2 * ASZ);
        u16* bl_s = (u16*)(base + buf * BLK + 2 * ASZ + BSZ);
        const u16* agh = p.ah + aoff + k0;
        const u16* agl = p.al + aoff + k0;
        const u16* bgh = p.bh + boff + k0;
        const u16* bgl = p.bl + boff + k0;
        {
            int row = tid >> 1, ch = tid & 1;
            size_t gs = (size_t)(m0 + row) * p.a_st + ch * 8;
            cpa16(smem_u32(ah_s + row * 24 + ch * 8), agh + gs);
            cpa16(smem_u32(al_s + row * 24 + ch * 8), agl + gs);
        }
        for (int j = tid; j < NTILE * 2; j += 256) {
            int row = j >> 1, ch = j & 1;
            size_t gs = (size_t)(n0 + row) * p.b_st + ch * 8;
            cpa16(smem_u32(bh_s + row * 24 + ch * 8), bgh + gs);
            cpa16(smem_u32(bl_s + row * 24 + ch * 8), bgl + gs);
        }
        asm volatile("cp.async.commit_group;" ::: "memory");
    };

    issue(0, 0);
    if (steps > 1) issue(1, 1);

    float acc[MT][4][4];
    #pragma unroll
    for (int i = 0; i < MT; i++)
        #pragma unroll
        for (int j = 0; j < 4; j++)
            #pragma unroll
            for (int c = 0; c < 4; c++) acc[i][j][c] = 0.0f;
    float nacc = 0.0f;

    for (int i = 0; i < steps; i++) {
        const int buf = i & 1;
        if (i + 1 < steps) asm volatile("cp.async.wait_group 1;" ::: "memory");
        else               asm volatile("cp.async.wait_group 0;" ::: "memory");
        __syncthreads();

        const u16* As_h = (const u16*)(base + buf * BLK);
        const u16* As_l = (const u16*)(base + buf * BLK + ASZ);
        const u16* Bs_h = (const u16*)(base + buf * BLK + 2 * ASZ);
        const u16* Bs_l = (const u16*)(base + buf * BLK + 2 * ASZ + BSZ);

        if (EPI == 4) {
            int row = tid >> 1, half = tid & 1;
            const __nv_bfloat162* xh = (const __nv_bfloat162*)(As_h + row * 24 + half * 8);
            const __nv_bfloat162* xl = (const __nv_bfloat162*)(As_l + row * 24 + half * 8);
            const float* kv = ksums + i * 16 + half * 8;
            #pragma unroll
            for (int t = 0; t < 4; t++) {
                float2 h2 = __bfloat1622float2(xh[t]);
                float2 l2 = __bfloat1622float2(xl[t]);
                nacc += (h2.x + l2.x) * kv[2 * t] + (h2.y + l2.y) * kv[2 * t + 1];
            }
        }

        const int r = lane >> 2, cq = lane & 3;
        u32 ahr[MT][4], alr[MT][4];
        #pragma unroll
        for (int im = 0; im < MT; im++) {
            const int mb = wm0 + im * 16;
            const u16* pa  = As_h + (mb + r) * 24 + 2 * cq;
            const u16* pa8 = As_h + (mb + r + 8) * 24 + 2 * cq;
            ahr[im][0] = *(const u32*)pa;
            ahr[im][1] = *(const u32*)pa8;
            ahr[im][2] = *(const u32*)(pa + 8);
            ahr[im][3] = *(const u32*)(pa8 + 8);
            const u16* qa  = As_l + (mb + r) * 24 + 2 * cq;
            const u16* qa8 = As_l + (mb + r + 8) * 24 + 2 * cq;
            alr[im][0] = *(const u32*)qa;
            alr[im][1] = *(const u32*)qa8;
            alr[im][2] = *(const u32*)(qa + 8);
            alr[im][3] = *(const u32*)(qa8 + 8);
        }
        #pragma unroll
        for (int in_ = 0; in_ < 4; in_++) {
            const int nb = wn0 + in_ * 8;
            const u16* pb = Bs_h + (nb + r) * 24 + 2 * cq;
            u32 bh2[2] = { *(const u32*)pb, *(const u32*)(pb + 8) };
            const u16* qb = Bs_l + (nb + r) * 24 + 2 * cq;
            u32 bl2[2] = { *(const u32*)qb, *(const u32*)(qb + 8) };
            #pragma unroll
            for (int im = 0; im < MT; im++) mma_bf16(acc[im][in_], ahr[im], bh2);
            #pragma unroll
            for (int im = 0; im < MT; im++) mma_bf16(acc[im][in_], alr[im], bh2);
            #pragma unroll
            for (int im = 0; im < MT; im++) mma_bf16(acc[im][in_], ahr[im], bl2);
        }
        __syncthreads();
        if (i + 2 < steps) issue(i + 2, buf);
    }

    if (EPI == 4) { snorm[tid] = nacc; __syncthreads(); }
    if (EPI == 1) { ksums[tid] = 0.0f; __syncthreads(); }

    // ---------------- epilogue ----------------
    const int lh = wn0 >> 6;
    #pragma unroll
    for (int im = 0; im < MT; im++) {
        const int la = wm0 + im * 16 + (lane >> 2);
        const int lb = la + 8;
        const int rA = m0 + la, rB = m0 + lb;
        float hnA = 0.0f, hnB = 0.0f, invA = 1.0f, invB = 1.0f;
        if (EPI == 2 || EPI == 3) {
            hnA = 0.5f * p.norm[(size_t)z * Sc + rA];
            hnB = 0.5f * p.norm[(size_t)z * Sc + rB];
        }
        if (EPI == 4) {
            invA = 1.0f / (snorm[2 * la] + snorm[2 * la + 1] + 1e-6f);
            invB = 1.0f / (snorm[2 * lb] + snorm[2 * lb + 1] + 1e-6f);
        }
        float sA = 0.0f, sB = 0.0f;
        #pragma unroll
        for (int in_ = 0; in_ < 4; in_++) {
            const int n = n0 + wn0 + in_ * 8 + ((lane & 3) << 1);
            float v0 = acc[im][in_][0], v1 = acc[im][in_][1];
            float v2 = acc[im][in_][2], v3 = acc[im][in_][3];
            if (EPI == 0 || EPI == 1) {
                float b0 = __ldg(p.bias + n), b1 = __ldg(p.bias + n + 1);
                v0 += b0; v1 += b1; v2 += b0; v3 += b1;
            } else if (EPI == 2 || EPI == 3) {
                v0 = __expf(v0 - hnA); v1 = __expf(v1 - hnA);
                v2 = __expf(v2 - hnB); v3 = __expf(v3 - hnB);
            } else if (EPI == 4) {
                v0 *= invA; v1 *= invA; v2 *= invB; v3 *= invB;
            }
            if (EPI == 1) { sA += v0 * v0 + v1 * v1; sB += v2 * v2 + v3 * v3; }
            if (EPI == 0 || EPI == 3) {
                *(float2*)(p.o0 + ooff + (size_t)rA * p.o_st + n) = make_float2(v0, v1);
                *(float2*)(p.o0 + ooff + (size_t)rB * p.o_st + n) = make_float2(v2, v3);
            } else {
                u16 h0, l0, h1, l1, h2, l2, h3, l3;
                bsplit(v0, h0, l0); bsplit(v1, h1, l1);
                bsplit(v2, h2, l2); bsplit(v3, h3, l3);
                size_t oA = ooff + (size_t)rA * p.o_st + n;
                size_t oB = ooff + (size_t)rB * p.o_st + n;
                *(u32*)(p.o_hi + oA) = (u32)h0 | ((u32)h1 << 16);
                *(u32*)(p.o_lo + oA) = (u32)l0 | ((u32)l1 << 16);
                *(u32*)(p.o_hi + oB) = (u32)h2 | ((u32)h3 << 16);
                *(u32*)(p.o_lo + oB) = (u32)l2 | ((u32)l3 << 16);
            }
        }
        if (EPI == 1) {
            atomicAdd(&ksums[la * 2 + lh], sA);
            atomicAdd(&ksums[lb * 2 + lh], sB);
        }
    }

    if (EPI == 1) {
        __syncthreads();
        int row = tid >> 1, hloc = tid & 1;
        int rg = m0 + row, b = rg >> 12, s = rg & 4095;
        int head = (n0 >> 6) + hloc;
        p.nrm_out[(size_t)(b * 16 + head) * Sc + s] = ksums[tid];
    }
}

// ---------------- SIMT kv aggregation (split-K over 8 s-chunks) ----------------
__global__ void __launch_bounds__(256)
kv_kernel(const float* __restrict__ KP, const float* __restrict__ V,
          float* __restrict__ KVp, float* __restrict__ KSp)
{
    __shared__ float Ks[16][128];
    __shared__ float Vs[16][64];
    const int tid = threadIdx.x, tx = tid & 15, ty = tid >> 4;
    const int bh = blockIdx.z, b = bh >> 4, h = bh & 15;
    const int rbase = blockIdx.x << 7;
    const int sbeg = blockIdx.y << 9;
    const float* Kpb = KP + (size_t)bh * Sc * Rc;
    const float* Vb  = V + (size_t)b * Sc * Dc + h * HDc;

    float acc[8][4];
    #pragma unroll
    for (int i = 0; i < 8; i++)
        #pragma unroll
        for (int j = 0; j < 4; j++) acc[i][j] = 0.0f;
    float ks[8];
    #pragma unroll
    for (int i = 0; i < 8; i++) ks[i] = 0.0f;
    const int vrow = tid >> 4, vdseg = (tid & 15) << 2;

    for (int s0 = sbeg; s0 < sbeg + 512; s0 += 16) {
        #pragma unroll
        for (int L = 0; L < 2; L++) {
            int f = tid + (L << 8), si = f >> 5, rseg = (f & 31) << 2;
            *(float4*)(&Ks[si][rseg]) =
                *(const float4*)(Kpb + (size_t)(s0 + si) * Rc + rbase + rseg);
        }
        *(float4*)(&Vs[vrow][vdseg]) = *(const float4*)(Vb + (size_t)(s0 + vrow) * Dc + vdseg);
        __syncthreads();
        #pragma unroll
        for (int kk = 0; kk < 16; kk++) {
            float a[8], bv[4];
            *(float4*)(a)     = *(const float4*)(&Ks[kk][ty << 3]);
            *(float4*)(a + 4) = *(const float4*)(&Ks[kk][(ty << 3) + 4]);
            *(float4*)(bv)    = *(const float4*)(&Vs[kk][tx << 2]);
            #pragma unroll
            for (int i = 0; i < 8; i++)
                #pragma unroll
                for (int j = 0; j < 4; j++) acc[i][j] = fmaf(a[i], bv[j], acc[i][j]);
            if (tx == 0) {
                #pragma unroll
                for (int i = 0; i < 8; i++) ks[i] += a[i];
            }
        }
        __syncthreads();
    }
    const size_t pb = (size_t)blockIdx.y * 64 + bh;
    float* kvo = KVp + pb * HDc * Rc;
    #pragma unroll
    for (int i = 0; i < 8; i++) {
        int r = rbase + (ty << 3) + i;
        #pragma unroll
        for (int j = 0; j < 4; j++)
            kvo[(size_t)((tx << 2) + j) * Rc + r] = acc[i][j];
    }
    if (tx == 0) {
        #pragma unroll
        for (int i = 0; i < 8; i++)
            KSp[pb * Rc + rbase + (ty << 3) + i] = ks[i];
    }
}

__global__ void kvreduce_kernel(const float* __restrict__ KVp, const float* __restrict__ KSp,
                                u16* __restrict__ KVTh, u16* __restrict__ KVTl,
                                float* __restrict__ KS)
{
    const size_t NELEM = (size_t)64 * HDc * Rc;
    size_t idx = (size_t)blockIdx.x * blockDim.x + threadIdx.x;
    if (idx < NELEM) {
        float s = 0.0f;
        #pragma unroll
        for (int c = 0; c < 8; c++) s += KVp[(size_t)c * NELEM + idx];
        u16 hv, lv; bsplit(s, hv, lv);
        KVTh[idx] = hv; KVTl[idx] = lv;
    }
    if (idx < (size_t)64 * Rc) {
        float s = 0.0f;
        #pragma unroll
        for (int c = 0; c < 8; c++) s += KSp[(size_t)c * 64 * Rc + idx];
        KS[idx] = s;
    }
}

// ---------------- launch ----------------
extern "C" void kernel_launch(void* const* d_in, const int* in_sizes, int n_in,
                              void* d_out, int out_size)
{
    (void)in_sizes; (void)n_in; (void)out_size;
    const float* x  = (const float*)d_in[0];
    const float* wq = (const float*)d_in[1];
    const float* bq = (const float*)d_in[2];
    const float* wk = (const float*)d_in[3];
    const float* bk = (const float*)d_in[4];
    const float* wv = (const float*)d_in[5];
    const float* bv = (const float*)d_in[6];
    const float* wo = (const float*)d_in[7];
    const float* bo = (const float*)d_in[8];
    const float* rf = (const float*)d_in[9];
    float* out = (float*)d_out;

    u16 *xh, *xl, *wqh, *wql, *wkh, *wkl, *wvh, *wvl, *woh, *wol;
    u16 *rfh, *rfl, *qh, *ql, *kh, *kl, *qph, *qpl, *kvth, *kvtl, *ath, *atl;
    float *vv, *nq, *nk, *kp, *kvp, *ksp, *ksum;
    cudaGetSymbolAddress((void**)&xh,  g_xh);   cudaGetSymbolAddress((void**)&xl,  g_xl);
    cudaGetSymbolAddress((void**)&wqh, g_wqh);  cudaGetSymbolAddress((void**)&wql, g_wql);
    cudaGetSymbolAddress((void**)&wkh, g_wkh);  cudaGetSymbolAddress((void**)&wkl, g_wkl);
    cudaGetSymbolAddress((void**)&wvh, g_wvh);  cudaGetSymbolAddress((void**)&wvl, g_wvl);
    cudaGetSymbolAddress((void**)&woh, g_woh);  cudaGetSymbolAddress((void**)&wol, g_wol);
    cudaGetSymbolAddress((void**)&rfh, g_rfh);  cudaGetSymbolAddress((void**)&rfl, g_rfl);
    cudaGetSymbolAddress((void**)&qh,  g_qh);   cudaGetSymbolAddress((void**)&ql,  g_ql);
    cudaGetSymbolAddress((void**)&kh,  g_kh);   cudaGetSymbolAddress((void**)&kl,  g_kl);
    cudaGetSymbolAddress((void**)&vv,  g_v);
    cudaGetSymbolAddress((void**)&nq,  g_nq);   cudaGetSymbolAddress((void**)&nk,  g_nk);
    cudaGetSymbolAddress((void**)&qph, g_qph);  cudaGetSymbolAddress((void**)&qpl, g_qpl);
    cudaGetSymbolAddress((void**)&kp,  g_kp);
    cudaGetSymbolAddress((void**)&kvp, g_kvp);  cudaGetSymbolAddress((void**)&ksp, g_ksp);
    cudaGetSymbolAddress((void**)&kvth, g_kvth);cudaGetSymbolAddress((void**)&kvtl, g_kvtl);
    cudaGetSymbolAddress((void**)&ksum, g_ksum);
    cudaGetSymbolAddress((void**)&ath, g_ath);  cudaGetSymbolAddress((void**)&atl, g_atl);

    const int SM128 = 2 * (2 * 128 * 48 + 2 * 128 * 48) + 2048;  // 51200
    const int SM64  = 2 * (2 * 128 * 48 + 2 * 64 * 48) + 2048;   // 38912
    cudaFuncSetAttribute(tgemm<128, 0>, cudaFuncAttributeMaxDynamicSharedMemorySize, SM128);
    cudaFuncSetAttribute(tgemm<128, 1>, cudaFuncAttributeMaxDynamicSharedMemorySize, SM128);
    cudaFuncSetAttribute(tgemm<128, 2>, cudaFuncAttributeMaxDynamicSharedMemorySize, SM128);
    cudaFuncSetAttribute(tgemm<128, 3>, cudaFuncAttributeMaxDynamicSharedMemorySize, SM128);
    cudaFuncSetAttribute(tgemm<64, 4>,  cudaFuncAttributeMaxDynamicSharedMemorySize, SM64);

    // splits
    split_kernel<<<2048, 256>>>((const float4*)x, xh, xl, Mtot * Dc / 4);
    split_kernel<<<512, 256>>>((const float4*)wq, wqh, wql, Dc * Dc / 4);
    split_kernel<<<512, 256>>>((const float4*)wk, wkh, wkl, Dc * Dc / 4);
    split_kernel<<<512, 256>>>((const float4*)wv, wvh, wvl, Dc * Dc / 4);
    split_kernel<<<512, 256>>>((const float4*)wo, woh, wol, Dc * Dc / 4);

    // projections (M=16384, N=1024, K=1024)
    dim3 gproj(Dc / 128, Mtot / 128, 1);
    TGP pj = {};
    pj.ah = xh; pj.al = xl; pj.a_ob = 0; pj.a_oh = 0; pj.a_st = Dc;
    pj.b_ob = 0; pj.b_oh = 0; pj.b_st = Dc; pj.K = Dc;
    pj.o_ob = 0; pj.o_oh = 0; pj.o_st = Dc;

    TGP pq = pj; pq.bh = wqh; pq.bl = wql; pq.bias = bq;
    pq.o_hi = qh; pq.o_lo = ql; pq.nrm_out = nq;
    tgemm<128, 1><<<gproj, 256, SM128>>>(pq);
    TGP pk = pj; pk.bh = wkh; pk.bl = wkl; pk.bias = bk;
    pk.o_hi = kh; pk.o_lo = kl; pk.nrm_out = nk;
    tgemm<128, 1><<<gproj, 256, SM128>>>(pk);
    TGP pv = pj; pv.bh = wvh; pv.bl = wvl; pv.bias = bv; pv.o0 = vv;
    tgemm<128, 0><<<gproj, 256, SM128>>>(pv);

    rft_kernel<<<(Hc * Rc * HDc + 255) / 256, 256>>>(rf, rfh, rfl);

    // feature maps (per bh: M=4096, N=256, K=64)
    dim3 gfeat(Rc / 128, Sc / 128, Bc * Hc);
    TGP pf = {};
    pf.a_ob = (long long)Sc * Dc; pf.a_oh = HDc; pf.a_st = Dc;
    pf.bh = rfh; pf.bl = rfl; pf.b_ob = 0; pf.b_oh = (long long)Rc * HDc; pf.b_st = HDc;
    pf.K = HDc;
    pf.o_ob = (long long)16 * Sc * Rc; pf.o_oh = (long long)Sc * Rc; pf.o_st = Rc;

    TGP pfq = pf; pfq.ah = qh; pfq.al = ql; pfq.norm = nq;
    pfq.o_hi = qph; pfq.o_lo = qpl;
    tgemm<128, 2><<<gfeat, 256, SM128>>>(pfq);
    TGP pfk = pf; pfk.ah = kh; pfk.al = kl; pfk.norm = nk; pfk.o0 = kp;
    tgemm<128, 3><<<gfeat, 256, SM128>>>(pfk);

    // kv aggregation
    dim3 gkv(Rc / 128, 8, Bc * Hc);
    kv_kernel<<<gkv, 256>>>(kp, vv, kvp, ksp);
    kvreduce_kernel<<<4096, 256>>>(kvp, ksp, kvth, kvtl, ksum);

    // attention readout (per bh: M=4096, N=64, K=256) + normalize
    dim3 gat(1, Sc / 128, Bc * Hc);
    TGP pa = {};
    pa.ah = qph; pa.al = qpl;
    pa.a_ob = (long long)16 * Sc * Rc; pa.a_oh = (long long)Sc * Rc; pa.a_st = Rc;
    pa.bh = kvth; pa.bl = kvtl;
    pa.b_ob = (long long)16 * HDc * Rc; pa.b_oh = (long long)HDc * Rc; pa.b_st = Rc;
    pa.K = Rc; pa.ksum = ksum;
    pa.o_hi = ath; pa.o_lo = atl;
    pa.o_ob = (long long)Sc * Dc; pa.o_oh = HDc; pa.o_st = Dc;
    tgemm<64, 4><<<gat, 256, SM64>>>(pa);

    // output projection
    TGP po = pj; po.ah = ath; po.al = atl; po.bh = woh; po.bl = wol;
    po.bias = bo; po.o0 = out;
    tgemm<128, 0><<<gproj, 256, SM128>>>(po);
}

// round 8
// speedup vs baseline: 2.5981x; 1.1457x over previous
#include <cuda_runtime.h>
#include <cuda_bf16.h>
#include <cstdint>
#include <math.h>

#define Bc 4
#define Sc 4096
#define Dc 1024
#define Hc 16
#define Rc 256
#define HDc 64
#define Mtot (Bc * Sc)
#define BK 32
#define RS 40      // smem row stride in u16 (32 data + 8 pad = 80B)

typedef unsigned short u16;
typedef uint32_t u32;

// ---------------- scratch (device globals) ----------------
__device__ u16 g_xh[(size_t)Mtot * Dc],  g_xl[(size_t)Mtot * Dc];
__device__ u16 g_wqh[Dc * Dc], g_wql[Dc * Dc];
__device__ u16 g_wkh[Dc * Dc], g_wkl[Dc * Dc];
__device__ u16 g_wvh[Dc * Dc], g_wvl[Dc * Dc];
__device__ u16 g_woh[Dc * Dc], g_wol[Dc * Dc];
__device__ u16 g_rfh[(size_t)Hc * Rc * HDc], g_rfl[(size_t)Hc * Rc * HDc];
__device__ u16 g_qh[(size_t)Mtot * Dc],  g_ql[(size_t)Mtot * Dc];
__device__ u16 g_kh[(size_t)Mtot * Dc],  g_kl[(size_t)Mtot * Dc];
__device__ float g_v[(size_t)Mtot * Dc];
__device__ float g_nq[(size_t)Bc * Hc * Sc], g_nk[(size_t)Bc * Hc * Sc];
__device__ u16 g_qph[(size_t)Bc * Hc * Sc * Rc], g_qpl[(size_t)Bc * Hc * Sc * Rc];
__device__ float g_kp[(size_t)Bc * Hc * Sc * Rc];
__device__ float g_kvp[(size_t)8 * Bc * Hc * HDc * Rc];
__device__ float g_ksp[(size_t)8 * Bc * Hc * Rc];
__device__ u16 g_kvth[(size_t)Bc * Hc * HDc * Rc], g_kvtl[(size_t)Bc * Hc * HDc * Rc];
__device__ float g_ksum[(size_t)Bc * Hc * Rc];
__device__ u16 g_ath[(size_t)Mtot * Dc], g_atl[(size_t)Mtot * Dc];

// ---------------- helpers ----------------
__device__ __forceinline__ u32 smem_u32(const void* p) {
    u32 a;
    asm("{ .reg .u64 t; cvta.to.shared.u64 t, %1; cvt.u32.u64 %0, t; }" : "=r"(a) : "l"(p));
    return a;
}
__device__ __forceinline__ void bsplit(float a, u16& h, u16& l) {
    __nv_bfloat16 hb = __float2bfloat16_rn(a);
    float lf = a - __bfloat162float(hb);
    __nv_bfloat16 lb = __float2bfloat16_rn(lf);
    h = __bfloat16_as_ushort(hb);
    l = __bfloat16_as_ushort(lb);
}
__device__ __forceinline__ void cpa16(u32 dst, const void* src) {
    asm volatile("cp.async.cg.shared.global [%0], [%1], 16;"
                 :: "r"(dst), "l"(__cvta_generic_to_global(src)) : "memory");
}
__device__ __forceinline__ void mma_bf16(float* c, const u32* A, const u32* B) {
    asm volatile(
        "mma.sync.aligned.m16n8k16.row.col.f32.bf16.bf16.f32 "
        "{%0,%1,%2,%3}, {%4,%5,%6,%7}, {%8,%9}, {%0,%1,%2,%3};"
        : "+f"(c[0]), "+f"(c[1]), "+f"(c[2]), "+f"(c[3])
        : "r"(A[0]), "r"(A[1]), "r"(A[2]), "r"(A[3]), "r"(B[0]), "r"(B[1]));
}
__device__ __forceinline__ void ldsm4(u32& r0, u32& r1, u32& r2, u32& r3, u32 addr) {
    asm volatile("ldmatrix.sync.aligned.m8n8.x4.shared.b16 {%0,%1,%2,%3}, [%4];"
                 : "=r"(r0), "=r"(r1), "=r"(r2), "=r"(r3) : "r"(addr));
}

// ---------------- split / transpose prep ----------------
__global__ void split_kernel(const float4* __restrict__ src, u16* __restrict__ hi,
                             u16* __restrict__ lo, int n4)
{
    for (int i = blockIdx.x * blockDim.x + threadIdx.x; i < n4; i += gridDim.x * blockDim.x) {
        float4 a = src[i];
        ushort4 hv, lv;
        bsplit(a.x, hv.x, lv.x); bsplit(a.y, hv.y, lv.y);
        bsplit(a.z, hv.z, lv.z); bsplit(a.w, hv.w, lv.w);
        *(ushort4*)(hi + (size_t)i * 4) = hv;
        *(ushort4*)(lo + (size_t)i * 4) = lv;
    }
}
__global__ void rft_kernel(const float* __restrict__ rf, u16* __restrict__ oh,
                           u16* __restrict__ ol)
{
    int idx = blockIdx.x * blockDim.x + threadIdx.x;
    if (idx >= Hc * Rc * HDc) return;
    int d = idx & 63, r = (idx >> 6) & 255, h = idx >> 14;
    float a = rf[((size_t)(h * HDc + d)) * Rc + r];
    u16 hv, lv; bsplit(a, hv, lv);
    oh[idx] = hv; ol[idx] = lv;
}

// ---------------- bf16x3 tensor GEMM engine (ldmatrix, BK=32) ----------------
// C[128 x NTILE] per CTA; C = A * B^T (fp32 accum), 3-pass bf16 (hh+lh+hl).
struct TGP {
    const u16 *ah, *al, *bh, *bl;
    long long a_ob, a_oh, b_ob, b_oh, o_ob, o_oh;
    int a_st, b_st, o_st, K;
    const float *bias, *norm, *ksum;
    float* o0;
    u16 *o_hi, *o_lo;
    float* nrm_out;
};

template<int NTILE, int EPI>
__global__ void __launch_bounds__(256, 2) tgemm(TGP p)
{
    extern __shared__ char smc[];
    const int tid = threadIdx.x, lane = tid & 31, wid = tid >> 5;
    const int z = blockIdx.z;
    const int m0 = blockIdx.y << 7, n0 = blockIdx.x * NTILE;

    constexpr int MT = (NTILE == 128) ? 4 : 2;
    const int wm0 = (NTILE == 128) ? ((wid & 1) << 6) : ((wid & 3) << 5);
    const int wn0 = (NTILE == 128) ? ((wid >> 1) << 5) : ((wid >> 2) << 5);

    constexpr int APL = 128 * RS * 2;       // bytes per A plane (80B rows)
    constexpr int BPL = NTILE * RS * 2;
    constexpr int BLK = 2 * APL + 2 * BPL;  // one stage (A hi/lo + B hi/lo)
    const u32 su = smem_u32(smc);
    float* const ksums = (float*)(smc + 2 * BLK);   // 256 f
    float* const snorm = ksums + 256;               // 256 f

    const size_t aoff = (size_t)p.a_ob * (z >> 4) + (size_t)p.a_oh * (z & 15);
    const size_t boff = (size_t)p.b_ob * (z >> 4) + (size_t)p.b_oh * (z & 15);
    const size_t ooff = (size_t)p.o_ob * (z >> 4) + (size_t)p.o_oh * (z & 15);

    if (EPI == 4) ksums[tid] = p.ksum[(size_t)z * Rc + tid];

    const int steps = p.K / BK;

    auto issue = [&](int step, int buf) {
        const int k0 = step * BK;
        const u32 sb = su + buf * BLK;
        const u16* agh = p.ah + aoff + k0;
        const u16* agl = p.al + aoff + k0;
        const u16* bgh = p.bh + boff + k0;
        const u16* bgl = p.bl + boff + k0;
        #pragma unroll
        for (int j = tid; j < 512; j += 256) {      // A: 128 rows x 4 chunks
            int row = j >> 2, ch = j & 3;
            size_t gs = (size_t)(m0 + row) * p.a_st + ch * 8;
            u32 so = row * (RS * 2) + ch * 16;
            cpa16(sb + so, agh + gs);
            cpa16(sb + APL + so, agl + gs);
        }
        #pragma unroll
        for (int j = tid; j < NTILE * 4; j += 256) { // B: NTILE rows x 4 chunks
            int row = j >> 2, ch = j & 3;
            size_t gs = (size_t)(n0 + row) * p.b_st + ch * 8;
            u32 so = row * (RS * 2) + ch * 16;
            cpa16(sb + 2 * APL + so, bgh + gs);
            cpa16(sb + 2 * APL + BPL + so, bgl + gs);
        }
        asm volatile("cp.async.commit_group;" ::: "memory");
    };

    issue(0, 0);
    if (steps > 1) issue(1, 1);

    float acc[MT][4][4];
    #pragma unroll
    for (int i = 0; i < MT; i++)
        #pragma unroll
        for (int j = 0; j < 4; j++)
            #pragma unroll
            for (int c = 0; c < 4; c++) acc[i][j][c] = 0.0f;
    float nacc = 0.0f;

    // ldmatrix lane-address offsets (bytes)
    const u32 aoff_lane = (lane & 15) * (RS * 2) + (lane >> 4) * 16;
    const u32 boff_lane = ((lane & 7) + ((lane >> 4) << 3)) * (RS * 2) + ((lane >> 3) & 1) * 16;

    for (int i = 0; i < steps; i++) {
        const int buf = i & 1;
        if (i + 1 < steps) asm volatile("cp.async.wait_group 1;" ::: "memory");
        else               asm volatile("cp.async.wait_group 0;" ::: "memory");
        __syncthreads();

        const u32 sb = su + buf * BLK;

        if (EPI == 4) {
            int row = tid >> 1, half16 = tid & 1;
            const __nv_bfloat162* xh = (const __nv_bfloat162*)(smc + buf * BLK
                                        + row * (RS * 2) + half16 * 32);
            const __nv_bfloat162* xl = (const __nv_bfloat162*)(smc + buf * BLK + APL
                                        + row * (RS * 2) + half16 * 32);
            const float* kv = ksums + i * BK + half16 * 16;
            #pragma unroll
            for (int t = 0; t < 8; t++) {
                float2 h2 = __bfloat1622float2(xh[t]);
                float2 l2 = __bfloat1622float2(xl[t]);
                nacc += (h2.x + l2.x) * kv[2 * t] + (h2.y + l2.y) * kv[2 * t + 1];
            }
        }

        #pragma unroll
        for (int half = 0; half < 2; half++) {       // two k16 sub-steps
            const u32 kb = half * 32;                // 16 u16 = 32 bytes
            u32 ahr[MT][4], alr[MT][4];
            #pragma unroll
            for (int im = 0; im < MT; im++) {
                u32 abase = sb + (wm0 + im * 16) * (RS * 2) + kb + aoff_lane;
                ldsm4(ahr[im][0], ahr[im][1], ahr[im][2], ahr[im][3], abase);
                ldsm4(alr[im][0], alr[im][1], alr[im][2], alr[im][3], abase + APL);
            }
            #pragma unroll
            for (int npair = 0; npair < 2; npair++) {  // n-blocks {2np, 2np+1}
                u32 bbase = sb + 2 * APL + (wn0 + npair * 16) * (RS * 2) + kb + boff_lane;
                u32 bh0, bh1, bh2_, bh3, bl0, bl1, bl2_, bl3;
                ldsm4(bh0, bh1, bh2_, bh3, bbase);
                ldsm4(bl0, bl1, bl2_, bl3, bbase + BPL);
                u32 bhA[2] = { bh0, bh1 }, bhB[2] = { bh2_, bh3 };
                u32 blA[2] = { bl0, bl1 }, blB[2] = { bl2_, bl3 };
                const int iA = npair * 2, iB = npair * 2 + 1;
                #pragma unroll
                for (int im = 0; im < MT; im++) mma_bf16(acc[im][iA], ahr[im], bhA);
                #pragma unroll
                for (int im = 0; im < MT; im++) mma_bf16(acc[im][iB], ahr[im], bhB);
                #pragma unroll
                for (int im = 0; im < MT; im++) mma_bf16(acc[im][iA], alr[im], bhA);
                #pragma unroll
                for (int im = 0; im < MT; im++) mma_bf16(acc[im][iB], alr[im], bhB);
                #pragma unroll
                for (int im = 0; im < MT; im++) mma_bf16(acc[im][iA], ahr[im], blA);
                #pragma unroll
                for (int im = 0; im < MT; im++) mma_bf16(acc[im][iB], ahr[im], blB);
            }
        }
        __syncthreads();
        if (i + 2 < steps) issue(i + 2, buf);
    }

    if (EPI == 4) { snorm[tid] = nacc; __syncthreads(); }
    if (EPI == 1) { ksums[tid] = 0.0f; __syncthreads(); }

    // ---------------- epilogue ----------------
    const int lh = wn0 >> 6;
    #pragma unroll
    for (int im = 0; im < MT; im++) {
        const int la = wm0 + im * 16 + (lane >> 2);
        const int lb = la + 8;
        const int rA = m0 + la, rB = m0 + lb;
        float hnA = 0.0f, hnB = 0.0f, invA = 1.0f, invB = 1.0f;
        if (EPI == 2 || EPI == 3) {
            hnA = 0.5f * p.norm[(size_t)z * Sc + rA];
            hnB = 0.5f * p.norm[(size_t)z * Sc + rB];
        }
        if (EPI == 4) {
            invA = 1.0f / (snorm[2 * la] + snorm[2 * la + 1] + 1e-6f);
            invB = 1.0f / (snorm[2 * lb] + snorm[2 * lb + 1] + 1e-6f);
        }
        float sA = 0.0f, sB = 0.0f;
        #pragma unroll
        for (int in_ = 0; in_ < 4; in_++) {
            const int n = n0 + wn0 + in_ * 8 + ((lane & 3) << 1);
            float v0 = acc[im][in_][0], v1 = acc[im][in_][1];
            float v2 = acc[im][in_][2], v3 = acc[im][in_][3];
            if (EPI == 0 || EPI == 1) {
                float b0 = __ldg(p.bias + n), b1 = __ldg(p.bias + n + 1);
                v0 += b0; v1 += b1; v2 += b0; v3 += b1;
            } else if (EPI == 2 || EPI == 3) {
                v0 = __expf(v0 - hnA); v1 = __expf(v1 - hnA);
                v2 = __expf(v2 - hnB); v3 = __expf(v3 - hnB);
            } else if (EPI == 4) {
                v0 *= invA; v1 *= invA; v2 *= invB; v3 *= invB;
            }
            if (EPI == 1) { sA += v0 * v0 + v1 * v1; sB += v2 * v2 + v3 * v3; }
            if (EPI == 0 || EPI == 3) {
                *(float2*)(p.o0 + ooff + (size_t)rA * p.o_st + n) = make_float2(v0, v1);
                *(float2*)(p.o0 + ooff + (size_t)rB * p.o_st + n) = make_float2(v2, v3);
            } else {
                u16 h0, l0, h1, l1, h2, l2, h3, l3;
                bsplit(v0, h0, l0); bsplit(v1, h1, l1);
                bsplit(v2, h2, l2); bsplit(v3, h3, l3);
                size_t oA = ooff + (size_t)rA * p.o_st + n;
                size_t oB = ooff + (size_t)rB * p.o_st + n;
                *(u32*)(p.o_hi + oA) = (u32)h0 | ((u32)h1 << 16);
                *(u32*)(p.o_lo + oA) = (u32)l0 | ((u32)l1 << 16);
                *(u32*)(p.o_hi + oB) = (u32)h2 | ((u32)h3 << 16);
                *(u32*)(p.o_lo + oB) = (u32)l2 | ((u32)l3 << 16);
            }
        }
        if (EPI == 1) {
            atomicAdd(&ksums[la * 2 + lh], sA);
            atomicAdd(&ksums[lb * 2 + lh], sB);
        }
    }

    if (EPI == 1) {
        __syncthreads();
        int row = tid >> 1, hloc = tid & 1;
        int rg = m0 + row, b = rg >> 12, s = rg & 4095;
        int head = (n0 >> 6) + hloc;
        p.nrm_out[(size_t)(b * 16 + head) * Sc + s] = ksums[tid];
    }
}

// ---------------- SIMT kv aggregation (split-K over 8 s-chunks) ----------------
__global__ void __launch_bounds__(256)
kv_kernel(const float* __restrict__ KP, const float* __restrict__ V,
          float* __restrict__ KVp, float* __restrict__ KSp)
{
    __shared__ float Ks[16][128];
    __shared__ float Vs[16][64];
    const int tid = threadIdx.x, tx = tid & 15, ty = tid >> 4;
    const int bh = blockIdx.z, b = bh >> 4, h = bh & 15;
    const int rbase = blockIdx.x << 7;
    const int sbeg = blockIdx.y << 9;
    const float* Kpb = KP + (size_t)bh * Sc * Rc;
    const float* Vb  = V + (size_t)b * Sc * Dc + h * HDc;

    float acc[8][4];
    #pragma unroll
    for (int i = 0; i < 8; i++)
        #pragma unroll
        for (int j = 0; j < 4; j++) acc[i][j] = 0.0f;
    float ks[8];
    #pragma unroll
    for (int i = 0; i < 8; i++) ks[i] = 0.0f;
    const int vrow = tid >> 4, vdseg = (tid & 15) << 2;

    for (int s0 = sbeg; s0 < sbeg + 512; s0 += 16) {
        #pragma unroll
        for (int L = 0; L < 2; L++) {
            int f = tid + (L << 8), si = f >> 5, rseg = (f & 31) << 2;
            *(float4*)(&Ks[si][rseg]) =
                *(const float4*)(Kpb + (size_t)(s0 + si) * Rc + rbase + rseg);
        }
        *(float4*)(&Vs[vrow][vdseg]) = *(const float4*)(Vb + (size_t)(s0 + vrow) * Dc + vdseg);
        __syncthreads();
        #pragma unroll
        for (int kk = 0; kk < 16; kk++) {
            float a[8], bv[4];
            *(float4*)(a)     = *(const float4*)(&Ks[kk][ty << 3]);
            *(float4*)(a + 4) = *(const float4*)(&Ks[kk][(ty << 3) + 4]);
            *(float4*)(bv)    = *(const float4*)(&Vs[kk][tx << 2]);
            #pragma unroll
            for (int i = 0; i < 8; i++)
                #pragma unroll
                for (int j = 0; j < 4; j++) acc[i][j] = fmaf(a[i], bv[j], acc[i][j]);
            if (tx == 0) {
                #pragma unroll
                for (int i = 0; i < 8; i++) ks[i] += a[i];
            }
        }
        __syncthreads();
    }
    const size_t pb = (size_t)blockIdx.y * 64 + bh;
    float* kvo = KVp + pb * HDc * Rc;
    #pragma unroll
    for (int i = 0; i < 8; i++) {
        int r = rbase + (ty << 3) + i;
        #pragma unroll
        for (int j = 0; j < 4; j++)
            kvo[(size_t)((tx << 2) + j) * Rc + r] = acc[i][j];
    }
    if (tx == 0) {
        #pragma unroll
        for (int i = 0; i < 8; i++)
            KSp[pb * Rc + rbase + (ty << 3) + i] = ks[i];
    }
}

__global__ void kvreduce_kernel(const float* __restrict__ KVp, const float* __restrict__ KSp,
                                u16* __restrict__ KVTh, u16* __restrict__ KVTl,
                                float* __restrict__ KS)
{
    const size_t NELEM = (size_t)64 * HDc * Rc;
    size_t idx = (size_t)blockIdx.x * blockDim.x + threadIdx.x;
    if (idx < NELEM) {
        float s = 0.0f;
        #pragma unroll
        for (int c = 0; c < 8; c++) s += KVp[(size_t)c * NELEM + idx];
        u16 hv, lv; bsplit(s, hv, lv);
        KVTh[idx] = hv; KVTl[idx] = lv;
    }
    if (idx < (size_t)64 * Rc) {
        float s = 0.0f;
        #pragma unroll
        for (int c = 0; c < 8; c++) s += KSp[(size_t)c * 64 * Rc + idx];
        KS[idx] = s;
    }
}

// ---------------- launch ----------------
extern "C" void kernel_launch(void* const* d_in, const int* in_sizes, int n_in,
                              void* d_out, int out_size)
{
    (void)in_sizes; (void)n_in; (void)out_size;
    const float* x  = (const float*)d_in[0];
    const float* wq = (const float*)d_in[1];
    const float* bq = (const float*)d_in[2];
    const float* wk = (const float*)d_in[3];
    const float* bk = (const float*)d_in[4];
    const float* wv = (const float*)d_in[5];
    const float* bv = (const float*)d_in[6];
    const float* wo = (const float*)d_in[7];
    const float* bo = (const float*)d_in[8];
    const float* rf = (const float*)d_in[9];
    float* out = (float*)d_out;

    u16 *xh, *xl, *wqh, *wql, *wkh, *wkl, *wvh, *wvl, *woh, *wol;
    u16 *rfh, *rfl, *qh, *ql, *kh, *kl, *qph, *qpl, *kvth, *kvtl, *ath, *atl;
    float *vv, *nq, *nk, *kp, *kvp, *ksp, *ksum;
    cudaGetSymbolAddress((void**)&xh,  g_xh);   cudaGetSymbolAddress((void**)&xl,  g_xl);
    cudaGetSymbolAddress((void**)&wqh, g_wqh);  cudaGetSymbolAddress((void**)&wql, g_wql);
    cudaGetSymbolAddress((void**)&wkh, g_wkh);  cudaGetSymbolAddress((void**)&wkl, g_wkl);
    cudaGetSymbolAddress((void**)&wvh, g_wvh);  cudaGetSymbolAddress((void**)&wvl, g_wvl);
    cudaGetSymbolAddress((void**)&woh, g_woh);  cudaGetSymbolAddress((void**)&wol, g_wol);
    cudaGetSymbolAddress((void**)&rfh, g_rfh);  cudaGetSymbolAddress((void**)&rfl, g_rfl);
    cudaGetSymbolAddress((void**)&qh,  g_qh);   cudaGetSymbolAddress((void**)&ql,  g_ql);
    cudaGetSymbolAddress((void**)&kh,  g_kh);   cudaGetSymbolAddress((void**)&kl,  g_kl);
    cudaGetSymbolAddress((void**)&vv,  g_v);
    cudaGetSymbolAddress((void**)&nq,  g_nq);   cudaGetSymbolAddress((void**)&nk,  g_nk);
    cudaGetSymbolAddress((void**)&qph, g_qph);  cudaGetSymbolAddress((void**)&qpl, g_qpl);
    cudaGetSymbolAddress((void**)&kp,  g_kp);
    cudaGetSymbolAddress((void**)&kvp, g_kvp);  cudaGetSymbolAddress((void**)&ksp, g_ksp);
    cudaGetSymbolAddress((void**)&kvth, g_kvth);cudaGetSymbolAddress((void**)&kvtl, g_kvtl);
    cudaGetSymbolAddress((void**)&ksum, g_ksum);
    cudaGetSymbolAddress((void**)&ath, g_ath);  cudaGetSymbolAddress((void**)&atl, g_atl);

    // smem: 2 stages * (2*A_plane + 2*B_plane) + 2KB
    const int SM128 = 2 * (2 * 128 * RS * 2 + 2 * 128 * RS * 2) + 2048;  // 83968
    const int SM64  = 2 * (2 * 128 * RS * 2 + 2 * 64 * RS * 2) + 2048;   // 63488
    cudaFuncSetAttribute(tgemm<128, 0>, cudaFuncAttributeMaxDynamicSharedMemorySize, SM128);
    cudaFuncSetAttribute(tgemm<128, 1>, cudaFuncAttributeMaxDynamicSharedMemorySize, SM128);
    cudaFuncSetAttribute(tgemm<128, 2>, cudaFuncAttributeMaxDynamicSharedMemorySize, SM128);
    cudaFuncSetAttribute(tgemm<128, 3>, cudaFuncAttributeMaxDynamicSharedMemorySize, SM128);
    cudaFuncSetAttribute(tgemm<64, 4>,  cudaFuncAttributeMaxDynamicSharedMemorySize, SM64);

    // splits
    split_kernel<<<2048, 256>>>((const float4*)x, xh, xl, Mtot * Dc / 4);
    split_kernel<<<512, 256>>>((const float4*)wq, wqh, wql, Dc * Dc / 4);
    split_kernel<<<512, 256>>>((const float4*)wk, wkh, wkl, Dc * Dc / 4);
    split_kernel<<<512, 256>>>((const float4*)wv, wvh, wvl, Dc * Dc / 4);
    split_kernel<<<512, 256>>>((const float4*)wo, woh, wol, Dc * Dc / 4);

    // projections (M=16384, N=1024, K=1024)
    dim3 gproj(Dc / 128, Mtot / 128, 1);
    TGP pj = {};
    pj.ah = xh; pj.al = xl; pj.a_ob = 0; pj.a_oh = 0; pj.a_st = Dc;
    pj.b_ob = 0; pj.b_oh = 0; pj.b_st = Dc; pj.K = Dc;
    pj.o_ob = 0; pj.o_oh = 0; pj.o_st = Dc;

    TGP pq = pj; pq.bh = wqh; pq.bl = wql; pq.bias = bq;
    pq.o_hi = qh; pq.o_lo = ql; pq.nrm_out = nq;
    tgemm<128, 1><<<gproj, 256, SM128>>>(pq);
    TGP pk = pj; pk.bh = wkh; pk.bl = wkl; pk.bias = bk;
    pk.o_hi = kh; pk.o_lo = kl; pk.nrm_out = nk;
    tgemm<128, 1><<<gproj, 256, SM128>>>(pk);
    TGP pv = pj; pv.bh = wvh; pv.bl = wvl; pv.bias = bv; pv.o0 = vv;
    tgemm<128, 0><<<gproj, 256, SM128>>>(pv);

    rft_kernel<<<(Hc * Rc * HDc + 255) / 256, 256>>>(rf, rfh, rfl);

    // feature maps (per bh: M=4096, N=256, K=64)
    dim3 gfeat(Rc / 128, Sc / 128, Bc * Hc);
    TGP pf = {};
    pf.a_ob = (long long)Sc * Dc; pf.a_oh = HDc; pf.a_st = Dc;
    pf.bh = rfh; pf.bl = rfl; pf.b_ob = 0; pf.b_oh = (long long)Rc * HDc; pf.b_st = HDc;
    pf.K = HDc;
    pf.o_ob = (long long)16 * Sc * Rc; pf.o_oh = (long long)Sc * Rc; pf.o_st = Rc;

    TGP pfq = pf; pfq.ah = qh; pfq.al = ql; pfq.norm = nq;
    pfq.o_hi = qph; pfq.o_lo = qpl;
    tgemm<128, 2><<<gfeat, 256, SM128>>>(pfq);
    TGP pfk = pf; pfk.ah = kh; pfk.al = kl; pfk.norm = nk; pfk.o0 = kp;
    tgemm<128, 3><<<gfeat, 256, SM128>>>(pfk);

    // kv aggregation
    dim3 gkv(Rc / 128, 8, Bc * Hc);
    kv_kernel<<<gkv, 256>>>(kp, vv, kvp, ksp);
    kvreduce_kernel<<<4096, 256>>>(kvp, ksp, kvth, kvtl, ksum);

    // attention readout (per bh: M=4096, N=64, K=256) + normalize
    dim3 gat(1, Sc / 128, Bc * Hc);
    TGP pa = {};
    pa.ah = qph; pa.al = qpl;
    pa.a_ob = (long long)16 * Sc * Rc; pa.a_oh = (long long)Sc * Rc; pa.a_st = Rc;
    pa.bh = kvth; pa.bl = kvtl;
    pa.b_ob = (long long)16 * HDc * Rc; pa.b_oh = (long long)HDc * Rc; pa.b_st = Rc;
    pa.K = Rc; pa.ksum = ksum;
    pa.o_hi = ath; pa.o_lo = atl;
    pa.o_ob = (long long)Sc * Dc; pa.o_oh = HDc; pa.o_st = Dc;
    tgemm<64, 4><<<gat, 256, SM64>>>(pa);

    // output projection
    TGP po = pj; po.ah = ath; po.al = atl; po.bh = woh; po.bl = wol;
    po.bias = bo; po.o0 = out;
    tgemm<128, 0><<<gproj, 256, SM128>>>(po);
}

// round 9
// speedup vs baseline: 2.7174x; 1.0459x over previous
#include <cuda_runtime.h>
#include <cuda_bf16.h>
#include <cstdint>
#include <math.h>

#define Bc 4
#define Sc 4096
#define Dc 1024
#define Hc 16
#define Rc 256
#define HDc 64
#define Mtot (Bc * Sc)
#define BK 32
#define RS 40      // smem row stride in u16 (32 data + 8 pad = 80B)

typedef unsigned short u16;
typedef uint32_t u32;

// ---------------- scratch (device globals) ----------------
__device__ u16 g_xh[(size_t)Mtot * Dc],  g_xl[(size_t)Mtot * Dc];
__device__ u16 g_wqh[Dc * Dc], g_wql[Dc * Dc];
__device__ u16 g_wkh[Dc * Dc], g_wkl[Dc * Dc];
__device__ u16 g_wvh[Dc * Dc], g_wvl[Dc * Dc];
__device__ u16 g_woh[Dc * Dc], g_wol[Dc * Dc];
__device__ u16 g_rfh[(size_t)Hc * Rc * HDc], g_rfl[(size_t)Hc * Rc * HDc];
__device__ u16 g_qh[(size_t)Mtot * Dc],  g_ql[(size_t)Mtot * Dc];
__device__ u16 g_kh[(size_t)Mtot * Dc],  g_kl[(size_t)Mtot * Dc];
__device__ u16 g_vth[(size_t)Mtot * Dc], g_vtl[(size_t)Mtot * Dc];   // V^T [d][m]
__device__ float g_nq[(size_t)Bc * Hc * Sc], g_nk[(size_t)Bc * Hc * Sc];
__device__ u16 g_qph[(size_t)Bc * Hc * Sc * Rc], g_qpl[(size_t)Bc * Hc * Sc * Rc];
__device__ u16 g_kpth[(size_t)Bc * Hc * Rc * Sc], g_kptl[(size_t)Bc * Hc * Rc * Sc]; // kp^T [bh][r][s]
__device__ float g_kvp[(size_t)Bc * Hc * 4 * Rc * HDc];   // kv split-K partials
__device__ float g_ksp[(size_t)Bc * Hc * 4 * Rc];
__device__ u16 g_kvth[(size_t)Bc * Hc * HDc * Rc], g_kvtl[(size_t)Bc * Hc * HDc * Rc];
__device__ float g_ksum[(size_t)Bc * Hc * Rc];
__device__ u16 g_ath[(size_t)Mtot * Dc], g_atl[(size_t)Mtot * Dc];

// ---------------- helpers ----------------
__device__ __forceinline__ u32 smem_u32(const void* p) {
    u32 a;
    asm("{ .reg .u64 t; cvta.to.shared.u64 t, %1; cvt.u32.u64 %0, t; }" : "=r"(a) : "l"(p));
    return a;
}
__device__ __forceinline__ void bsplit(float a, u16& h, u16& l) {
    __nv_bfloat16 hb = __float2bfloat16_rn(a);
    float lf = a - __bfloat162float(hb);
    __nv_bfloat16 lb = __float2bfloat16_rn(lf);
    h = __bfloat16_as_ushort(hb);
    l = __bfloat16_as_ushort(lb);
}
__device__ __forceinline__ void cpa16(u32 dst, const void* src) {
    asm volatile("cp.async.cg.shared.global [%0], [%1], 16;"
                 :: "r"(dst), "l"(__cvta_generic_to_global(src)) : "memory");
}
__device__ __forceinline__ void mma_bf16(float* c, const u32* A, const u32* B) {
    asm volatile(
        "mma.sync.aligned.m16n8k16.row.col.f32.bf16.bf16.f32 "
        "{%0,%1,%2,%3}, {%4,%5,%6,%7}, {%8,%9}, {%0,%1,%2,%3};"
        : "+f"(c[0]), "+f"(c[1]), "+f"(c[2]), "+f"(c[3])
        : "r"(A[0]), "r"(A[1]), "r"(A[2]), "r"(A[3]), "r"(B[0]), "r"(B[1]));
}
__device__ __forceinline__ void ldsm4(u32& r0, u32& r1, u32& r2, u32& r3, u32 addr) {
    asm volatile("ldmatrix.sync.aligned.m8n8.x4.shared.b16 {%0,%1,%2,%3}, [%4];"
                 : "=r"(r0), "=r"(r1), "=r"(r2), "=r"(r3) : "r"(addr));
}

// ---------------- split / transpose prep ----------------
__global__ void split_kernel(const float4* __restrict__ src, u16* __restrict__ hi,
                             u16* __restrict__ lo, int n4)
{
    for (int i = blockIdx.x * blockDim.x + threadIdx.x; i < n4; i += gridDim.x * blockDim.x) {
        float4 a = src[i];
        ushort4 hv, lv;
        bsplit(a.x, hv.x, lv.x); bsplit(a.y, hv.y, lv.y);
        bsplit(a.z, hv.z, lv.z); bsplit(a.w, hv.w, lv.w);
        *(ushort4*)(hi + (size_t)i * 4) = hv;
        *(ushort4*)(lo + (size_t)i * 4) = lv;
    }
}
__global__ void rft_kernel(const float* __restrict__ rf, u16* __restrict__ oh,
                           u16* __restrict__ ol)
{
    int idx = blockIdx.x * blockDim.x + threadIdx.x;
    if (idx >= Hc * Rc * HDc) return;
    int d = idx & 63, r = (idx >> 6) & 255, h = idx >> 14;
    float a = rf[((size_t)(h * HDc + d)) * Rc + r];
    u16 hv, lv; bsplit(a, hv, lv);
    oh[idx] = hv; ol[idx] = lv;
}

// ---------------- bf16x3 tensor GEMM engine (ldmatrix, BK=32) ----------------
// C[128 x NTILE] per CTA; C = A * B^T (fp32 accum), 3-pass bf16 (hh+lh+hl).
// EPI: 0 +bias(col)->f32 | 1 +bias(col)->split + per-head rownorm
//      2 exp(v-0.5*norm[row])->split | 4 normalize by in-loop (A.ksum)->split
//      5 exp(v-0.5*norm[col])->split | 6 +bias(row)->split
//      8 split-K partial: raw f32 out + in-loop A-rowsum partial (chunk=blockIdx.x)
struct TGP {
    const u16 *ah, *al, *bh, *bl;
    long long a_ob, a_oh, b_ob, b_oh, o_ob, o_oh;
    int a_st, b_st, o_st, K;
    const float *bias, *norm, *ksum;
    float* o0;
    u16 *o_hi, *o_lo;
    float* nrm_out;
};

template<int NTILE, int EPI>
__global__ void __launch_bounds__(256, 2) tgemm(TGP p)
{
    extern __shared__ char smc[];
    const int tid = threadIdx.x, lane = tid & 31, wid = tid >> 5;
    const int z = blockIdx.z;
    const int m0 = blockIdx.y << 7;
    const int chunk = (EPI == 8) ? blockIdx.x : 0;
    const int n0 = (EPI == 8) ? 0 : blockIdx.x * NTILE;

    constexpr int MT = (NTILE == 128) ? 4 : 2;
    const int wm0 = (NTILE == 128) ? ((wid & 1) << 6) : ((wid & 3) << 5);
    const int wn0 = (NTILE == 128) ? ((wid >> 1) << 5) : ((wid >> 2) << 5);

    constexpr int APL = 128 * RS * 2;       // bytes per A plane (80B rows)
    constexpr int BPL = NTILE * RS * 2;
    constexpr int BLK = 2 * APL + 2 * BPL;  // one stage
    const u32 su = smem_u32(smc);
    float* const ksums = (float*)(smc + 2 * BLK);   // 256 f
    float* const snorm = ksums + 256;               // 256 f

    size_t aoff = (size_t)p.a_ob * (z >> 4) + (size_t)p.a_oh * (z & 15);
    size_t boff = (size_t)p.b_ob * (z >> 4) + (size_t)p.b_oh * (z & 15);
    const size_t ooff = (size_t)p.o_ob * (z >> 4) + (size_t)p.o_oh * (z & 15);
    if (EPI == 8) { aoff += (size_t)chunk * 1024; boff += (size_t)chunk * 1024; }

    if (EPI == 4) ksums[tid] = p.ksum[(size_t)z * Rc + tid];

    const int steps = p.K / BK;

    auto issue = [&](int step, int buf) {
        const int k0 = step * BK;
        const u32 sb = su + buf * BLK;
        const u16* agh = p.ah + aoff + k0;
        const u16* agl = p.al + aoff + k0;
        const u16* bgh = p.bh + boff + k0;
        const u16* bgl = p.bl + boff + k0;
        #pragma unroll
        for (int j = tid; j < 512; j += 256) {
            int row = j >> 2, ch = j & 3;
            size_t gs = (size_t)(m0 + row) * p.a_st + ch * 8;
            u32 so = row * (RS * 2) + ch * 16;
            cpa16(sb + so, agh + gs);
            cpa16(sb + APL + so, agl + gs);
        }
        #pragma unroll
        for (int j = tid; j < NTILE * 4; j += 256) {
            int row = j >> 2, ch = j & 3;
            size_t gs = (size_t)(n0 + row) * p.b_st + ch * 8;
            u32 so = row * (RS * 2) + ch * 16;
            cpa16(sb + 2 * APL + so, bgh + gs);
            cpa16(sb + 2 * APL + BPL + so, bgl + gs);
        }
        asm volatile("cp.async.commit_group;" ::: "memory");
    };

    issue(0, 0);
    if (steps > 1) issue(1, 1);

    float acc[MT][4][4];
    #pragma unroll
    for (int i = 0; i < MT; i++)
        #pragma unroll
        for (int j = 0; j < 4; j++)
            #pragma unroll
            for (int c = 0; c < 4; c++) acc[i][j][c] = 0.0f;
    float nacc = 0.0f;

    const u32 aoff_lane = (lane & 15) * (RS * 2) + (lane >> 4) * 16;
    const u32 boff_lane = ((lane & 7) + ((lane >> 4) << 3)) * (RS * 2) + ((lane >> 3) & 1) * 16;

    for (int i = 0; i < steps; i++) {
        const int buf = i & 1;
        if (i + 1 < steps) asm volatile("cp.async.wait_group 1;" ::: "memory");
        else               asm volatile("cp.async.wait_group 0;" ::: "memory");
        __syncthreads();

        const u32 sb = su + buf * BLK;

        if (EPI == 4 || EPI == 8) {
            int row = tid >> 1, half16 = tid & 1;
            const __nv_bfloat162* xh = (const __nv_bfloat162*)(smc + buf * BLK
                                        + row * (RS * 2) + half16 * 32);
            const __nv_bfloat162* xl = (const __nv_bfloat162*)(smc + buf * BLK + APL
                                        + row * (RS * 2) + half16 * 32);
            if (EPI == 4) {
                const float* kv = ksums + i * BK + half16 * 16;
                #pragma unroll
                for (int t = 0; t < 8; t++) {
                    float2 h2 = __bfloat1622float2(xh[t]);
                    float2 l2 = __bfloat1622float2(xl[t]);
                    nacc += (h2.x + l2.x) * kv[2 * t] + (h2.y + l2.y) * kv[2 * t + 1];
                }
            } else {
                #pragma unroll
                for (int t = 0; t < 8; t++) {
                    float2 h2 = __bfloat1622float2(xh[t]);
                    float2 l2 = __bfloat1622float2(xl[t]);
                    nacc += h2.x + l2.x + h2.y + l2.y;
                }
            }
        }

        #pragma unroll
        for (int half = 0; half < 2; half++) {
            const u32 kb = half * 32;
            u32 ahr[MT][4], alr[MT][4];
            #pragma unroll
            for (int im = 0; im < MT; im++) {
                u32 abase = sb + (wm0 + im * 16) * (RS * 2) + kb + aoff_lane;
                ldsm4(ahr[im][0], ahr[im][1], ahr[im][2], ahr[im][3], abase);
                ldsm4(alr[im][0], alr[im][1], alr[im][2], alr[im][3], abase + APL);
            }
            #pragma unroll
            for (int npair = 0; npair < 2; npair++) {
                u32 bbase = sb + 2 * APL + (wn0 + npair * 16) * (RS * 2) + kb + boff_lane;
                u32 bh0, bh1, bh2_, bh3, bl0, bl1, bl2_, bl3;
                ldsm4(bh0, bh1, bh2_, bh3, bbase);
                ldsm4(bl0, bl1, bl2_, bl3, bbase + BPL);
                u32 bhA[2] = { bh0, bh1 }, bhB[2] = { bh2_, bh3 };
                u32 blA[2] = { bl0, bl1 }, blB[2] = { bl2_, bl3 };
                const int iA = npair * 2, iB = npair * 2 + 1;
                #pragma unroll
                for (int im = 0; im < MT; im++) mma_bf16(acc[im][iA], ahr[im], bhA);
                #pragma unroll
                for (int im = 0; im < MT; im++) mma_bf16(acc[im][iB], ahr[im], bhB);
                #pragma unroll
                for (int im = 0; im < MT; im++) mma_bf16(acc[im][iA], alr[im], bhA);
                #pragma unroll
                for (int im = 0; im < MT; im++) mma_bf16(acc[im][iB], alr[im], bhB);
                #pragma unroll
                for (int im = 0; im < MT; im++) mma_bf16(acc[im][iA], ahr[im], blA);
                #pragma unroll
                for (int im = 0; im < MT; im++) mma_bf16(acc[im][iB], ahr[im], blB);
            }
        }
        __syncthreads();
        if (i + 2 < steps) issue(i + 2, buf);
    }

    if (EPI == 4 || EPI == 8) { snorm[tid] = nacc; __syncthreads(); }
    if (EPI == 1) { ksums[tid] = 0.0f; __syncthreads(); }

    // ---------------- epilogue ----------------
    const int lh = wn0 >> 6;
    #pragma unroll
    for (int im = 0; im < MT; im++) {
        const int la = wm0 + im * 16 + (lane >> 2);
        const int lb = la + 8;
        const int rA = m0 + la, rB = m0 + lb;
        float hnA = 0.0f, hnB = 0.0f, invA = 1.0f, invB = 1.0f;
        float bA = 0.0f, bB = 0.0f;
        if (EPI == 2) {
            hnA = 0.5f * p.norm[(size_t)z * Sc + rA];
            hnB = 0.5f * p.norm[(size_t)z * Sc + rB];
        }
        if (EPI == 6) {
            bA = __ldg(p.bias + rA);
            bB = __ldg(p.bias + rB);
        }
        if (EPI == 4) {
            invA = 1.0f / (snorm[2 * la] + snorm[2 * la + 1] + 1e-6f);
            invB = 1.0f / (snorm[2 * lb] + snorm[2 * lb + 1] + 1e-6f);
        }
        float sA = 0.0f, sB = 0.0f;
        #pragma unroll
        for (int in_ = 0; in_ < 4; in_++) {
            const int n = n0 + wn0 + in_ * 8 + ((lane & 3) << 1);
            float v0 = acc[im][in_][0], v1 = acc[im][in_][1];
            float v2 = acc[im][in_][2], v3 = acc[im][in_][3];
            if (EPI == 0 || EPI == 1) {
                float b0 = __ldg(p.bias + n), b1 = __ldg(p.bias + n + 1);
                v0 += b0; v1 += b1; v2 += b0; v3 += b1;
            } else if (EPI == 6) {
                v0 += bA; v1 += bA; v2 += bB; v3 += bB;
            } else if (EPI == 2) {
                v0 = __expf(v0 - hnA); v1 = __expf(v1 - hnA);
                v2 = __expf(v2 - hnB); v3 = __expf(v3 - hnB);
            } else if (EPI == 5) {
                float hn0 = 0.5f * __ldg(p.norm + (size_t)z * Sc + n);
                float hn1 = 0.5f * __ldg(p.norm + (size_t)z * Sc + n + 1);
                v0 = __expf(v0 - hn0); v1 = __expf(v1 - hn1);
                v2 = __expf(v2 - hn0); v3 = __expf(v3 - hn1);
            } else if (EPI == 4) {
                v0 *= invA; v1 *= invA; v2 *= invB; v3 *= invB;
            }
            if (EPI == 1) { sA += v0 * v0 + v1 * v1; sB += v2 * v2 + v3 * v3; }
            if (EPI == 0) {
                *(float2*)(p.o0 + ooff + (size_t)rA * p.o_st + n) = make_float2(v0, v1);
                *(float2*)(p.o0 + ooff + (size_t)rB * p.o_st + n) = make_float2(v2, v3);
            } else if (EPI == 8) {
                float* b8 = p.o0 + (((size_t)z * 4 + chunk) << 14);   // *(256*64)
                *(float2*)(b8 + (size_t)rA * 64 + n) = make_float2(v0, v1);
                *(float2*)(b8 + (size_t)rB * 64 + n) = make_float2(v2, v3);
            } else {
                u16 h0, l0, h1, l1, h2, l2, h3, l3;
                bsplit(v0, h0, l0); bsplit(v1, h1, l1);
                bsplit(v2, h2, l2); bsplit(v3, h3, l3);
                size_t oA = ooff + (size_t)rA * p.o_st + n;
                size_t oB = ooff + (size_t)rB * p.o_st + n;
                *(u32*)(p.o_hi + oA) = (u32)h0 | ((u32)h1 << 16);
                *(u32*)(p.o_lo + oA) = (u32)l0 | ((u32)l1 << 16);
                *(u32*)(p.o_hi + oB) = (u32)h2 | ((u32)h3 << 16);
                *(u32*)(p.o_lo + oB) = (u32)l2 | ((u32)l3 << 16);
            }
        }
        if (EPI == 1) {
            atomicAdd(&ksums[la * 2 + lh], sA);
            atomicAdd(&ksums[lb * 2 + lh], sB);
        }
    }

    if (EPI == 1) {
        __syncthreads();
        int row = tid >> 1, hloc = tid & 1;
        int rg = m0 + row, b = rg >> 12, s = rg & 4095;
        int head = (n0 >> 6) + hloc;
        p.nrm_out[(size_t)(b * 16 + head) * Sc + s] = ksums[tid];
    }
    if (EPI == 8) {
        if (tid < 128)
            p.nrm_out[(((size_t)z * 4 + chunk) << 8) + m0 + tid] =
                snorm[2 * tid] + snorm[2 * tid + 1];
    }
}

// ---------------- kv final reduce: partials -> KVT split planes + ksum ----------------
__global__ void kvfinal_kernel(const float* __restrict__ kvp, const float* __restrict__ ksp,
                               u16* __restrict__ kvth, u16* __restrict__ kvtl,
                               float* __restrict__ ks)
{
    size_t idx = (size_t)blockIdx.x * 256 + threadIdx.x;   // 1M total
    int r = (int)(idx & 255), d = (int)((idx >> 8) & 63), bh = (int)(idx >> 14);
    float s = 0.0f;
    #pragma unroll
    for (int c = 0; c < 4; c++)
        s += kvp[(((size_t)bh * 4 + c) << 14) + (r << 6) + d];
    u16 hv, lv; bsplit(s, hv, lv);
    size_t o = ((size_t)bh << 14) + (d << 8) + r;
    kvth[o] = hv; kvtl[o] = lv;
    if (idx < (size_t)64 * 256) {
        int bh2 = (int)(idx >> 8), r2 = (int)(idx & 255);
        float t = 0.0f;
        #pragma unroll
        for (int c = 0; c < 4; c++) t += ksp[((size_t)(bh2 * 4 + c) << 8) + r2];
        ks[idx] = t;
    }
}

// ---------------- launch ----------------
extern "C" void kernel_launch(void* const* d_in, const int* in_sizes, int n_in,
                              void* d_out, int out_size)
{
    (void)in_sizes; (void)n_in; (void)out_size;
    const float* x  = (const float*)d_in[0];
    const float* wq = (const float*)d_in[1];
    const float* bq = (const float*)d_in[2];
    const float* wk = (const float*)d_in[3];
    const float* bk = (const float*)d_in[4];
    const float* wv = (const float*)d_in[5];
    const float* bv = (const float*)d_in[6];
    const float* wo = (const float*)d_in[7];
    const float* bo = (const float*)d_in[8];
    const float* rf = (const float*)d_in[9];
    float* out = (float*)d_out;

    u16 *xh, *xl, *wqh, *wql, *wkh, *wkl, *wvh, *wvl, *woh, *wol;
    u16 *rfh, *rfl, *qh, *ql, *kh, *kl, *vth, *vtl, *qph, *qpl;
    u16 *kpth, *kptl, *kvth, *kvtl, *ath, *atl;
    float *nq, *nk, *kvp, *ksp, *ksum;
    cudaGetSymbolAddress((void**)&xh,  g_xh);   cudaGetSymbolAddress((void**)&xl,  g_xl);
    cudaGetSymbolAddress((void**)&wqh, g_wqh);  cudaGetSymbolAddress((void**)&wql, g_wql);
    cudaGetSymbolAddress((void**)&wkh, g_wkh);  cudaGetSymbolAddress((void**)&wkl, g_wkl);
    cudaGetSymbolAddress((void**)&wvh, g_wvh);  cudaGetSymbolAddress((void**)&wvl, g_wvl);
    cudaGetSymbolAddress((void**)&woh, g_woh);  cudaGetSymbolAddress((void**)&wol, g_wol);
    cudaGetSymbolAddress((void**)&rfh, g_rfh);  cudaGetSymbolAddress((void**)&rfl, g_rfl);
    cudaGetSymbolAddress((void**)&qh,  g_qh);   cudaGetSymbolAddress((void**)&ql,  g_ql);
    cudaGetSymbolAddress((void**)&kh,  g_kh);   cudaGetSymbolAddress((void**)&kl,  g_kl);
    cudaGetSymbolAddress((void**)&vth, g_vth);  cudaGetSymbolAddress((void**)&vtl, g_vtl);
    cudaGetSymbolAddress((void**)&nq,  g_nq);   cudaGetSymbolAddress((void**)&nk,  g_nk);
    cudaGetSymbolAddress((void**)&qph, g_qph);  cudaGetSymbolAddress((void**)&qpl, g_qpl);
    cudaGetSymbolAddress((void**)&kpth, g_kpth);cudaGetSymbolAddress((void**)&kptl, g_kptl);
    cudaGetSymbolAddress((void**)&kvp, g_kvp);  cudaGetSymbolAddress((void**)&ksp, g_ksp);
    cudaGetSymbolAddress((void**)&kvth, g_kvth);cudaGetSymbolAddress((void**)&kvtl, g_kvtl);
    cudaGetSymbolAddress((void**)&ksum, g_ksum);
    cudaGetSymbolAddress((void**)&ath, g_ath);  cudaGetSymbolAddress((void**)&atl, g_atl);

    const int SM128 = 2 * (2 * 128 * RS * 2 + 2 * 128 * RS * 2) + 2048;  // 83968
    const int SM64  = 2 * (2 * 128 * RS * 2 + 2 * 64 * RS * 2) + 2048;   // 63488
    cudaFuncSetAttribute(tgemm<128, 0>, cudaFuncAttributeMaxDynamicSharedMemorySize, SM128);
    cudaFuncSetAttribute(tgemm<128, 1>, cudaFuncAttributeMaxDynamicSharedMemorySize, SM128);
    cudaFuncSetAttribute(tgemm<128, 2>, cudaFuncAttributeMaxDynamicSharedMemorySize, SM128);
    cudaFuncSetAttribute(tgemm<128, 5>, cudaFuncAttributeMaxDynamicSharedMemorySize, SM128);
    cudaFuncSetAttribute(tgemm<128, 6>, cudaFuncAttributeMaxDynamicSharedMemorySize, SM128);
    cudaFuncSetAttribute(tgemm<64, 4>,  cudaFuncAttributeMaxDynamicSharedMemorySize, SM64);
    cudaFuncSetAttribute(tgemm<64, 8>,  cudaFuncAttributeMaxDynamicSharedMemorySize, SM64);

    // splits
    split_kernel<<<2048, 256>>>((const float4*)x, xh, xl, Mtot * Dc / 4);
    split_kernel<<<512, 256>>>((const float4*)wq, wqh, wql, Dc * Dc / 4);
    split_kernel<<<512, 256>>>((const float4*)wk, wkh, wkl, Dc * Dc / 4);
    split_kernel<<<512, 256>>>((const float4*)wv, wvh, wvl, Dc * Dc / 4);
    split_kernel<<<512, 256>>>((const float4*)wo, woh, wol, Dc * Dc / 4);
    rft_kernel<<<(Hc * Rc * HDc + 255) / 256, 256>>>(rf, rfh, rfl);

    // Q/K projections (M=16384, N=1024, K=1024)
    dim3 gproj(Dc / 128, Mtot / 128, 1);
    TGP pj = {};
    pj.ah = xh; pj.al = xl; pj.a_ob = 0; pj.a_oh = 0; pj.a_st = Dc;
    pj.b_ob = 0; pj.b_oh = 0; pj.b_st = Dc; pj.K = Dc;
    pj.o_ob = 0; pj.o_oh = 0; pj.o_st = Dc;

    TGP pq = pj; pq.bh = wqh; pq.bl = wql; pq.bias = bq;
    pq.o_hi = qh; pq.o_lo = ql; pq.nrm_out = nq;
    tgemm<128, 1><<<gproj, 256, SM128>>>(pq);
    TGP pk = pj; pk.bh = wkh; pk.bl = wkl; pk.bias = bk;
    pk.o_hi = kh; pk.o_lo = kl; pk.nrm_out = nk;
    tgemm<128, 1><<<gproj, 256, SM128>>>(pk);

    // V projection TRANSPOSED: C[d, m] = wv * x^T  (M=1024, N=16384, K=1024)
    dim3 gvt(Mtot / 128, Dc / 128, 1);
    TGP pv = {};
    pv.ah = wvh; pv.al = wvl; pv.a_ob = 0; pv.a_oh = 0; pv.a_st = Dc;
    pv.bh = xh;  pv.bl = xl;  pv.b_ob = 0; pv.b_oh = 0; pv.b_st = Dc;
    pv.K = Dc; pv.bias = bv;
    pv.o_hi = vth; pv.o_lo = vtl; pv.o_ob = 0; pv.o_oh = 0; pv.o_st = Mtot;
    tgemm<128, 6><<<gvt, 256, SM128>>>(pv);

    // feature-Q (per bh: M=4096 s, N=256 r, K=64)
    dim3 gfeat(Rc / 128, Sc / 128, Bc * Hc);
    TGP pfq = {};
    pfq.ah = qh; pfq.al = ql;
    pfq.a_ob = (long long)Sc * Dc; pfq.a_oh = HDc; pfq.a_st = Dc;
    pfq.bh = rfh; pfq.bl = rfl;
    pfq.b_ob = 0; pfq.b_oh = (long long)Rc * HDc; pfq.b_st = HDc;
    pfq.K = HDc; pfq.norm = nq;
    pfq.o_hi = qph; pfq.o_lo = qpl;
    pfq.o_ob = (long long)16 * Sc * Rc; pfq.o_oh = (long long)Sc * Rc; pfq.o_st = Rc;
    tgemm<128, 2><<<gfeat, 256, SM128>>>(pfq);

    // feature-K TRANSPOSED (per bh: M=256 r, N=4096 s, K=64) -> kp^T split
    dim3 gfkt(Sc / 128, Rc / 128, Bc * Hc);
    TGP pfk = {};
    pfk.ah = rfh; pfk.al = rfl;
    pfk.a_ob = 0; pfk.a_oh = (long long)Rc * HDc; pfk.a_st = HDc;
    pfk.bh = kh; pfk.bl = kl;
    pfk.b_ob = (long long)Sc * Dc; pfk.b_oh = HDc; pfk.b_st = Dc;
    pfk.K = HDc; pfk.norm = nk;
    pfk.o_hi = kpth; pfk.o_lo = kptl;
    pfk.o_ob = (long long)16 * Rc * Sc; pfk.o_oh = (long long)Rc * Sc; pfk.o_st = Sc;
    tgemm<128, 5><<<gfkt, 256, SM128>>>(pfk);

    // kv aggregation GEMM (per bh: M=256 r, N=64 d, K=4096 s, split-K x4)
    dim3 gkv(4, Rc / 128, Bc * Hc);
    TGP pkv = {};
    pkv.ah = kpth; pkv.al = kptl;
    pkv.a_ob = (long long)16 * Rc * Sc; pkv.a_oh = (long long)Rc * Sc; pkv.a_st = Sc;
    pkv.bh = vth; pkv.bl = vtl;
    pkv.b_ob = 4096; pkv.b_oh = (long long)64 * Mtot; pkv.b_st = Mtot;
    pkv.K = 1024;
    pkv.o0 = kvp; pkv.nrm_out = ksp;
    tgemm<64, 8><<<gkv, 256, SM64>>>(pkv);

    kvfinal_kernel<<<4096, 256>>>(kvp, ksp, kvth, kvtl, ksum);

    // attention readout (per bh: M=4096 s, N=64 d, K=256 r) + normalize
    dim3 gat(1, Sc / 128, Bc * Hc);
    TGP pa = {};
    pa.ah = qph; pa.al = qpl;
    pa.a_ob = (long long)16 * Sc * Rc; pa.a_oh = (long long)Sc * Rc; pa.a_st = Rc;
    pa.bh = kvth; pa.bl = kvtl;
    pa.b_ob = (long long)16 * HDc * Rc; pa.b_oh = (long long)HDc * Rc; pa.b_st = Rc;
    pa.K = Rc; pa.ksum = ksum;
    pa.o_hi = ath; pa.o_lo = atl;
    pa.o_ob = (long long)Sc * Dc; pa.o_oh = HDc; pa.o_st = Dc;
    tgemm<64, 4><<<gat, 256, SM64>>>(pa);

    // output projection
    TGP po = pj; po.ah = ath; po.al = atl; po.bh = woh; po.bl = wol;
    po.bias = bo; po.o0 = out;
    tgemm<128, 0><<<gproj, 256, SM128>>>(po);
}